// round 8
// baseline (speedup 1.0000x reference)
#include <cuda_runtime.h>
#include <cuda_bf16.h>
#include <math.h>
#include <stdint.h>

#define BBATCH 2
#define TT 2048
#define CC 1024
#define HH 16
#define C3 3072
#define MTOT 4096
#define KP 512          // k-pairs (1024/2)

// ---------------------------------------------------------------------------
// Scratch (__device__ globals; no allocation allowed)
// ---------------------------------------------------------------------------
__device__ float    g_q [(size_t)MTOT * CC];             // fp32 Q (QKV epilogue)
__device__ uint32_t g_KH[(size_t)BBATCH*HH*TT*32];       // K bf16-hi packed [b,h,key,dp]
__device__ uint32_t g_KL[(size_t)BBATCH*HH*TT*32];       // K bf16-lo packed
__device__ float    g_V [(size_t)BBATCH*HH*TT*64];       // V tf32 [b,h,key,d]
__device__ uint32_t g_XH[(size_t)MTOT*KP];               // x split, A-plane layout
__device__ uint32_t g_XL[(size_t)MTOT*KP];
__device__ uint32_t g_WQh[(size_t)KP*C3];                // W_qkv split, B-plane layout
__device__ uint32_t g_WQl[(size_t)KP*C3];
__device__ uint32_t g_WOh[(size_t)KP*CC];                // W_out split
__device__ uint32_t g_WOl[(size_t)KP*CC];
__device__ uint32_t g_ATh[(size_t)MTOT*KP];              // attention out split (A-plane)
__device__ uint32_t g_ATl[(size_t)MTOT*KP];

// ---------------------------------------------------------------------------
// helpers
// ---------------------------------------------------------------------------
__device__ __forceinline__ float tf32_rna(float x) {
    float r; asm("cvt.rna.tf32.f32 %0, %1;" : "=f"(r) : "f"(x)); return r;
}
__device__ __forceinline__ void bsplit(float x, uint16_t& h, uint16_t& l) {
    __nv_bfloat16 hb = __float2bfloat16_rn(x);
    float hf = __bfloat162float(hb);
    __nv_bfloat16 lb = __float2bfloat16_rn(x - hf);
    h = __bfloat16_as_ushort(hb);
    l = __bfloat16_as_ushort(lb);
}
__device__ __forceinline__ uint32_t pk(uint16_t a, uint16_t b) {
    return (uint32_t)a | ((uint32_t)b << 16);
}
__device__ __forceinline__ void split_pk2(float x0, float x1, uint32_t& hi, uint32_t& lo) {
    uint16_t h0, l0, h1, l1;
    bsplit(x0, h0, l0); bsplit(x1, h1, l1);
    hi = pk(h0, h1); lo = pk(l0, l1);
}
__device__ __forceinline__ uint32_t sptr(const void* p) {
    return (uint32_t)__cvta_generic_to_shared(p);
}
__device__ __forceinline__ void ldm4(uint32_t* r, uint32_t addr) {
    asm volatile("ldmatrix.sync.aligned.m8n8.x4.shared.b16 {%0,%1,%2,%3}, [%4];"
        : "=r"(r[0]), "=r"(r[1]), "=r"(r[2]), "=r"(r[3]) : "r"(addr));
}
#define CP16(dst, src) \
    asm volatile("cp.async.cg.shared.global [%0], [%1], 16;\n" :: "r"(dst), "l"(src))
#define CP_COMMIT() asm volatile("cp.async.commit_group;\n")
#define CP_WAIT_ALL() asm volatile("cp.async.wait_group 0;\n")

__device__ __forceinline__ void mma16(float* d, const uint32_t* a,
                                      uint32_t b0, uint32_t b1) {
    asm volatile(
        "mma.sync.aligned.m16n8k16.row.col.f32.bf16.bf16.f32 "
        "{%0,%1,%2,%3}, {%4,%5,%6,%7}, {%8,%9}, {%0,%1,%2,%3};\n"
        : "+f"(d[0]), "+f"(d[1]), "+f"(d[2]), "+f"(d[3])
        : "r"(a[0]), "r"(a[1]), "r"(a[2]), "r"(a[3]), "r"(b0), "r"(b1));
}
__device__ __forceinline__ void mma8(float* d,
                                     uint32_t a0, uint32_t a1, uint32_t a2, uint32_t a3,
                                     uint32_t b0, uint32_t b1) {
    asm volatile(
        "mma.sync.aligned.m16n8k8.row.col.f32.tf32.tf32.f32 "
        "{%0,%1,%2,%3}, {%4,%5,%6,%7}, {%8,%9}, {%0,%1,%2,%3};\n"
        : "+f"(d[0]), "+f"(d[1]), "+f"(d[2]), "+f"(d[3])
        : "r"(a0), "r"(a1), "r"(a2), "r"(a3), "r"(b0), "r"(b1));
}

// ---------------------------------------------------------------------------
// Prep kernels
// ---------------------------------------------------------------------------
__global__ void split_A_kernel(const float* __restrict__ src,
                               uint32_t* __restrict__ hi, uint32_t* __restrict__ lo,
                               int nquads) {
    int i = blockIdx.x * blockDim.x + threadIdx.x;
    if (i >= nquads) return;
    float4 v = ((const float4*)src)[i];
    uint32_t h0, l0, h1, l1;
    split_pk2(v.x, v.y, h0, l0);
    split_pk2(v.z, v.w, h1, l1);
    ((uint2*)hi)[i] = make_uint2(h0, h1);
    ((uint2*)lo)[i] = make_uint2(l0, l1);
}
__global__ void split_B_kernel(const float* __restrict__ W,
                               uint32_t* __restrict__ hi, uint32_t* __restrict__ lo,
                               int N) {
    int i = blockIdx.x * blockDim.x + threadIdx.x;
    int nq = N >> 2;
    if (i >= KP * nq) return;
    int kp = i / nq, c4 = (i - kp * nq) * 4;
    const float* p0 = W + (size_t)(2 * kp) * N + c4;
    float4 r0 = *(const float4*)p0;
    float4 r1 = *(const float4*)(p0 + N);
    uint16_t a, b, c, d;
    uint4 hv, lv;
    bsplit(r0.x, a, c); bsplit(r1.x, b, d); hv.x = pk(a, b); lv.x = pk(c, d);
    bsplit(r0.y, a, c); bsplit(r1.y, b, d); hv.y = pk(a, b); lv.y = pk(c, d);
    bsplit(r0.z, a, c); bsplit(r1.z, b, d); hv.z = pk(a, b); lv.z = pk(c, d);
    bsplit(r0.w, a, c); bsplit(r1.w, b, d); hv.w = pk(a, b); lv.w = pk(c, d);
    *(uint4*)(hi + (size_t)kp * N + c4) = hv;
    *(uint4*)(lo + (size_t)kp * N + c4) = lv;
}

// ---------------------------------------------------------------------------
// GEMM: pre-split bf16x3, single-sync cp.async double-buffer, ldmatrix A.
// BM=BN=128, BK=32 (16 kpairs), 256 threads (8 warps 2x4, warp tile 64x32).
// ---------------------------------------------------------------------------
#define ASTG (128*20)
#define BSTG (16*136)
#define GEMM_SMEM_BYTES ((4*ASTG + 4*BSTG) * 4)   // 75776

template<int EPI>
__global__ void __launch_bounds__(256, 2)
gemm_sp(const uint32_t* __restrict__ Aph, const uint32_t* __restrict__ Apl,
        const uint32_t* __restrict__ Bph, const uint32_t* __restrict__ Bpl,
        const float* __restrict__ bias, float* __restrict__ Cout, int N) {
    extern __shared__ uint32_t smg[];
    uint32_t* sAh = smg;
    uint32_t* sAl = smg + 2 * ASTG;
    uint32_t* sBh = smg + 4 * ASTG;
    uint32_t* sBl = smg + 4 * ASTG + 2 * BSTG;

    const int tid = threadIdx.x;
    const int lane = tid & 31, wid = tid >> 5;
    const int g = lane >> 2, t = lane & 3;
    const int wm = (wid >> 2) * 64, wn = (wid & 3) * 32;
    const int bx = blockIdx.x, by = blockIdx.y;

    float acc[4][4][4];
#pragma unroll
    for (int i = 0; i < 4; i++)
#pragma unroll
        for (int j = 0; j < 4; j++)
#pragma unroll
            for (int r = 0; r < 4; r++) acc[i][j][r] = 0.0f;

    auto load_stage = [&](int st, int kp0) {
#pragma unroll
        for (int i = 0; i < 2; i++) {
            int id = tid + i * 256;
            int row = id >> 2, c = (id & 3) * 4;
            size_t go = (size_t)(by * 128 + row) * KP + kp0 + c;
            CP16(sptr(&sAh[st * ASTG + row * 20 + c]), Aph + go);
            CP16(sptr(&sAl[st * ASTG + row * 20 + c]), Apl + go);
        }
#pragma unroll
        for (int i = 0; i < 2; i++) {
            int id = tid + i * 256;
            int row = id >> 5, c = (id & 31) * 4;
            size_t go = (size_t)(kp0 + row) * N + bx * 128 + c;
            CP16(sptr(&sBh[st * BSTG + row * 136 + c]), Bph + go);
            CP16(sptr(&sBl[st * BSTG + row * 136 + c]), Bpl + go);
        }
    };

    load_stage(0, 0);
    CP_COMMIT();

    const int NK = KP / 16;   // 32
    const int arow = lane & 15;
    const int ahalf = (lane >> 4) * 4;

    for (int k = 0; k < NK; k++) {
        int st = k & 1;
        CP_WAIT_ALL();
        __syncthreads();
        // issue next stage NOW; it flies during this stage's compute
        if (k + 1 < NK) load_stage(st ^ 1, (k + 1) * 16);
        CP_COMMIT();

#pragma unroll
        for (int s = 0; s < 2; s++) {
            const int acol = s * 8 + ahalf;
            uint32_t af[4][4], bf[4][2];
            // lo(A) x hi(B)
#pragma unroll
            for (int mt = 0; mt < 4; mt++)
                ldm4(af[mt], sptr(&sAl[st * ASTG + (wm + mt * 16 + arow) * 20 + acol]));
#pragma unroll
            for (int nt = 0; nt < 4; nt++) {
                bf[nt][0] = sBh[st * BSTG + (s * 8 + t) * 136 + wn + nt * 8 + g];
                bf[nt][1] = sBh[st * BSTG + (s * 8 + t + 4) * 136 + wn + nt * 8 + g];
            }
#pragma unroll
            for (int mt = 0; mt < 4; mt++)
#pragma unroll
                for (int nt = 0; nt < 4; nt++)
                    mma16(acc[mt][nt], af[mt], bf[nt][0], bf[nt][1]);
            // hi(A) x hi(B)
#pragma unroll
            for (int mt = 0; mt < 4; mt++)
                ldm4(af[mt], sptr(&sAh[st * ASTG + (wm + mt * 16 + arow) * 20 + acol]));
#pragma unroll
            for (int mt = 0; mt < 4; mt++)
#pragma unroll
                for (int nt = 0; nt < 4; nt++)
                    mma16(acc[mt][nt], af[mt], bf[nt][0], bf[nt][1]);
            // hi(A) x lo(B)
#pragma unroll
            for (int nt = 0; nt < 4; nt++) {
                bf[nt][0] = sBl[st * BSTG + (s * 8 + t) * 136 + wn + nt * 8 + g];
                bf[nt][1] = sBl[st * BSTG + (s * 8 + t + 4) * 136 + wn + nt * 8 + g];
            }
#pragma unroll
            for (int mt = 0; mt < 4; mt++)
#pragma unroll
                for (int nt = 0; nt < 4; nt++)
                    mma16(acc[mt][nt], af[mt], bf[nt][0], bf[nt][1]);
        }
        // no trailing barrier: next iteration's sync covers the overwrite hazard
    }

    // ---------------- epilogue ----------------
#pragma unroll
    for (int mt = 0; mt < 4; mt++) {
        int row = by * 128 + wm + mt * 16 + g;
#pragma unroll
        for (int nt = 0; nt < 4; nt++) {
            int col = bx * 128 + wn + nt * 8 + 2 * t;
            float b0v = bias[col], b1v = bias[col + 1];
            float v0 = acc[mt][nt][0] + b0v, v1 = acc[mt][nt][1] + b1v;
            float v2 = acc[mt][nt][2] + b0v, v3 = acc[mt][nt][3] + b1v;
            if (EPI == 0) {
                *(float2*)&Cout[(size_t)row * N + col]       = make_float2(v0, v1);
                *(float2*)&Cout[(size_t)(row + 8) * N + col] = make_float2(v2, v3);
            } else {
                int region = bx >> 3;   // uniform per block: 0=Q, 1=K, 2=V
                int b = row >> 11, key = row & (TT - 1);
                if (region == 0) {
                    *(float2*)&g_q[(size_t)row * CC + col]       = make_float2(v0, v1);
                    *(float2*)&g_q[(size_t)(row + 8) * CC + col] = make_float2(v2, v3);
                } else if (region == 1) {
                    int c2 = col - CC;
                    int h = c2 >> 6, dp = (c2 & 63) >> 1;
                    size_t r0 = ((size_t)(b * HH + h) * TT + key) * 32 + dp;
                    size_t r1 = r0 + 8 * 32;
                    uint32_t hh, ll;
                    split_pk2(v0, v1, hh, ll); g_KH[r0] = hh; g_KL[r0] = ll;
                    split_pk2(v2, v3, hh, ll); g_KH[r1] = hh; g_KL[r1] = ll;
                } else {
                    int c2 = col - 2 * CC;
                    int h = c2 >> 6, d = c2 & 63;
                    size_t r0 = ((size_t)(b * HH + h) * TT + key) * 64 + d;
                    size_t r1 = r0 + 8 * 64;
                    *(float2*)&g_V[r0] = make_float2(tf32_rna(v0), tf32_rna(v1));
                    *(float2*)&g_V[r1] = make_float2(tf32_rna(v2), tf32_rna(v3));
                }
            }
        }
    }
}

// ---------------------------------------------------------------------------
// Flash attention: 256 threads (8 warps), q-tile 128, K/V tile 64,
// single-sync double-buffer, ldmatrix K frags, bf16x3 scores, tf32 P*V.
// grid (T/128, H, B).
// ---------------------------------------------------------------------------
#define KSTG (64*36)            // u32 per K stage per plane
#define VSTG (64*72)            // floats per V stage
#define PS_STRIDE 68
#define ATTN_SMEM_WORDS (4*KSTG + 2*VSTG + 8*16*PS_STRIDE)   // 27136
#define ATTN_SMEM_BYTES (ATTN_SMEM_WORDS * 4)                // 108544

__global__ void __launch_bounds__(256, 2)
attn_sp() {
    extern __shared__ uint32_t sma[];
    uint32_t* sKh = sma;                       // [2][64][36]
    uint32_t* sKl = sma + 2 * KSTG;            // [2][64][36]
    float*    sV  = (float*)(sma + 4 * KSTG);  // [2][64][72]
    float*    sP  = (float*)(sma + 4 * KSTG + 2 * VSTG);  // [8][16][68]

    const int tid = threadIdx.x;
    const int lane = tid & 31, wid = tid >> 5;
    const int g = lane >> 2, t = lane & 3;
    const int qt = blockIdx.x, h = blockIdx.y, b = blockIdx.z;
    const int bh = b * HH + h;
    const uint32_t* KHb = g_KH + (size_t)bh * TT * 32;
    const uint32_t* KLb = g_KL + (size_t)bh * TT * 32;
    const float*    Vb  = g_V  + (size_t)bh * TT * 64;

    const int q0 = qt * 128 + wid * 16;
    const int grow = b * TT + q0;

    // Q fragments (bf16 hi/lo packed pairs), scaled 1/8, loaded once.
    uint32_t qh[4][4], ql[4][4];
    {
        const float* qr0 = g_q + (size_t)(grow + g) * CC + h * 64;
        const float* qr1 = g_q + (size_t)(grow + g + 8) * CC + h * 64;
#pragma unroll
        for (int s = 0; s < 4; s++) {
            int p0 = s * 8 + t, p1 = s * 8 + t + 4;
            split_pk2(qr0[2*p0] * 0.125f, qr0[2*p0+1] * 0.125f, qh[s][0], ql[s][0]);
            split_pk2(qr1[2*p0] * 0.125f, qr1[2*p0+1] * 0.125f, qh[s][1], ql[s][1]);
            split_pk2(qr0[2*p1] * 0.125f, qr0[2*p1+1] * 0.125f, qh[s][2], ql[s][2]);
            split_pk2(qr1[2*p1] * 0.125f, qr1[2*p1+1] * 0.125f, qh[s][3], ql[s][3]);
        }
    }

    float mrow0 = -INFINITY, mrow1 = -INFINITY;
    float lrow0 = 0.0f, lrow1 = 0.0f;
    float oacc[8][4];
#pragma unroll
    for (int nt = 0; nt < 8; nt++)
#pragma unroll
        for (int r = 0; r < 4; r++) oacc[nt][r] = 0.0f;

    float* Pw = sP + wid * 16 * PS_STRIDE;

    auto load_tile = [&](int st, int kt) {
#pragma unroll
        for (int i = 0; i < 2; i++) {
            int id = tid + i * 256;
            int row = id >> 3, c = (id & 7) * 4;
            size_t go = (size_t)(kt + row) * 32 + c;
            CP16(sptr(&sKh[st * KSTG + row * 36 + c]), KHb + go);
            CP16(sptr(&sKl[st * KSTG + row * 36 + c]), KLb + go);
        }
#pragma unroll
        for (int i = 0; i < 4; i++) {
            int id = tid + i * 256;
            int row = id >> 4, c = (id & 15) * 4;
            CP16(sptr(&sV[st * VSTG + row * 72 + c]), Vb + (size_t)(kt + row) * 64 + c);
        }
    };

    load_tile(0, 0);
    CP_COMMIT();

    const int krow = lane & 15;
    const int khalf = (lane >> 4) * 4;

    for (int kti = 0; kti < TT / 64; kti++) {
        int st = kti & 1;
        CP_WAIT_ALL();
        __syncthreads();
        if (kti + 1 < TT / 64) load_tile(st ^ 1, (kti + 1) * 64);
        CP_COMMIT();

        // S = Q K^T  (bf16x3) — ldmatrix K frags
        float sacc[8][4];
#pragma unroll
        for (int nt = 0; nt < 8; nt++)
#pragma unroll
            for (int r = 0; r < 4; r++) sacc[nt][r] = 0.0f;

#pragma unroll
        for (int npp = 0; npp < 4; npp++) {
            const int kb = npp * 16;
#pragma unroll
            for (int s = 0; s < 4; s++) {
                uint32_t kf[4];
                ldm4(kf, sptr(&sKh[st * KSTG + (kb + krow) * 36 + s * 8 + khalf]));
                mma16(sacc[2*npp],     ql[s], kf[0], kf[2]);
                mma16(sacc[2*npp + 1], ql[s], kf[1], kf[3]);
                mma16(sacc[2*npp],     qh[s], kf[0], kf[2]);
                mma16(sacc[2*npp + 1], qh[s], kf[1], kf[3]);
                ldm4(kf, sptr(&sKl[st * KSTG + (kb + krow) * 36 + s * 8 + khalf]));
                mma16(sacc[2*npp],     qh[s], kf[0], kf[2]);
                mma16(sacc[2*npp + 1], qh[s], kf[1], kf[3]);
            }
        }

        // Online softmax
        float mx0 = -INFINITY, mx1 = -INFINITY;
#pragma unroll
        for (int nt = 0; nt < 8; nt++) {
            mx0 = fmaxf(mx0, fmaxf(sacc[nt][0], sacc[nt][1]));
            mx1 = fmaxf(mx1, fmaxf(sacc[nt][2], sacc[nt][3]));
        }
        mx0 = fmaxf(mx0, __shfl_xor_sync(0xffffffffu, mx0, 1));
        mx0 = fmaxf(mx0, __shfl_xor_sync(0xffffffffu, mx0, 2));
        mx1 = fmaxf(mx1, __shfl_xor_sync(0xffffffffu, mx1, 1));
        mx1 = fmaxf(mx1, __shfl_xor_sync(0xffffffffu, mx1, 2));

        float mn0 = fmaxf(mrow0, mx0);
        float mn1 = fmaxf(mrow1, mx1);
        float c0 = __expf(mrow0 - mn0);
        float c1 = __expf(mrow1 - mn1);
        lrow0 *= c0; lrow1 *= c1;
#pragma unroll
        for (int nt = 0; nt < 8; nt++) {
            oacc[nt][0] *= c0; oacc[nt][1] *= c0;
            oacc[nt][2] *= c1; oacc[nt][3] *= c1;
        }

        float s0 = 0.0f, s1 = 0.0f;
#pragma unroll
        for (int nt = 0; nt < 8; nt++) {
            float p00 = tf32_rna(__expf(sacc[nt][0] - mn0));
            float p01 = tf32_rna(__expf(sacc[nt][1] - mn0));
            float p10 = tf32_rna(__expf(sacc[nt][2] - mn1));
            float p11 = tf32_rna(__expf(sacc[nt][3] - mn1));
            s0 += p00 + p01;
            s1 += p10 + p11;
            int col = nt * 8 + 2 * t;
            *(float2*)&Pw[(g    ) * PS_STRIDE + col] = make_float2(p00, p01);
            *(float2*)&Pw[(g + 8) * PS_STRIDE + col] = make_float2(p10, p11);
        }
        s0 += __shfl_xor_sync(0xffffffffu, s0, 1);
        s0 += __shfl_xor_sync(0xffffffffu, s0, 2);
        s1 += __shfl_xor_sync(0xffffffffu, s1, 1);
        s1 += __shfl_xor_sync(0xffffffffu, s1, 2);
        lrow0 += s0; lrow1 += s1;
        mrow0 = mn0; mrow1 = mn1;

        __syncwarp();

        // O += P V   (tf32)
        const float* Vst = sV + st * VSTG;
#pragma unroll
        for (int kk = 0; kk < 8; kk++) {
            uint32_t p0 = __float_as_uint(Pw[(g    ) * PS_STRIDE + kk * 8 + t]);
            uint32_t p1 = __float_as_uint(Pw[(g + 8) * PS_STRIDE + kk * 8 + t]);
            uint32_t p2 = __float_as_uint(Pw[(g    ) * PS_STRIDE + kk * 8 + t + 4]);
            uint32_t p3 = __float_as_uint(Pw[(g + 8) * PS_STRIDE + kk * 8 + t + 4]);
#pragma unroll
            for (int nt = 0; nt < 8; nt++) {
                uint32_t b0 = __float_as_uint(Vst[(kk * 8 + t    ) * 72 + nt * 8 + g]);
                uint32_t b1 = __float_as_uint(Vst[(kk * 8 + t + 4) * 72 + nt * 8 + g]);
                mma8(oacc[nt], p0, p1, p2, p3, b0, b1);
            }
        }
        // no trailing barrier: next iteration's sync covers the overwrite hazard
    }

    // Epilogue: normalize, write split bf16 planes (A-layout for out-proj)
    const float inv0 = 1.0f / lrow0;
    const float inv1 = 1.0f / lrow1;
    const size_t r0 = (size_t)(grow + g) * KP;
    const size_t r1 = (size_t)(grow + g + 8) * KP;
#pragma unroll
    for (int nt = 0; nt < 8; nt++) {
        int kp = h * 32 + nt * 4 + t;
        uint32_t hh, ll;
        split_pk2(oacc[nt][0] * inv0, oacc[nt][1] * inv0, hh, ll);
        g_ATh[r0 + kp] = hh; g_ATl[r0 + kp] = ll;
        split_pk2(oacc[nt][2] * inv1, oacc[nt][3] * inv1, hh, ll);
        g_ATh[r1 + kp] = hh; g_ATl[r1 + kp] = ll;
    }
}

// ---------------------------------------------------------------------------
// Launch
// ---------------------------------------------------------------------------
extern "C" void kernel_launch(void* const* d_in, const int* in_sizes, int n_in,
                              void* d_out, int out_size) {
    const float* x    = (const float*)d_in[0];
    const float* Wqkv = (const float*)d_in[1];
    const float* bqkv = (const float*)d_in[2];
    const float* Wout = (const float*)d_in[3];
    const float* bout = (const float*)d_in[4];
    float* out = (float*)d_out;

    uint32_t *XH, *XL, *WQh, *WQl, *WOh, *WOl, *ATh, *ATl;
    cudaGetSymbolAddress((void**)&XH,  g_XH);
    cudaGetSymbolAddress((void**)&XL,  g_XL);
    cudaGetSymbolAddress((void**)&WQh, g_WQh);
    cudaGetSymbolAddress((void**)&WQl, g_WQl);
    cudaGetSymbolAddress((void**)&WOh, g_WOh);
    cudaGetSymbolAddress((void**)&WOl, g_WOl);
    cudaGetSymbolAddress((void**)&ATh, g_ATh);
    cudaGetSymbolAddress((void**)&ATl, g_ATl);

    cudaFuncSetAttribute(gemm_sp<0>, cudaFuncAttributeMaxDynamicSharedMemorySize,
                         GEMM_SMEM_BYTES);
    cudaFuncSetAttribute(gemm_sp<1>, cudaFuncAttributeMaxDynamicSharedMemorySize,
                         GEMM_SMEM_BYTES);
    cudaFuncSetAttribute(attn_sp, cudaFuncAttributeMaxDynamicSharedMemorySize,
                         ATTN_SMEM_BYTES);

    // Prep: split x and weights
    {
        int nq = MTOT * CC / 4;
        split_A_kernel<<<(nq + 255) / 256, 256>>>(x, XH, XL, nq);
    }
    split_B_kernel<<<(KP * (C3 / 4) + 255) / 256, 256>>>(Wqkv, WQh, WQl, C3);
    split_B_kernel<<<(KP * (CC / 4) + 255) / 256, 256>>>(Wout, WOh, WOl, CC);

    // 1) QKV projection with fused Q/K/V-layout epilogue
    gemm_sp<1><<<dim3(C3 / 128, MTOT / 128), 256, GEMM_SMEM_BYTES>>>(
        XH, XL, WQh, WQl, bqkv, nullptr, C3);

    // 2) Flash attention
    attn_sp<<<dim3(TT / 128, HH, BBATCH), 256, ATTN_SMEM_BYTES>>>();

    // 3) Output projection
    gemm_sp<0><<<dim3(CC / 128, MTOT / 128), 256, GEMM_SMEM_BYTES>>>(
        ATh, ATl, WOh, WOl, bout, out, CC);
}

// round 10
// speedup vs baseline: 1.1373x; 1.1373x over previous
#include <cuda_runtime.h>
#include <cuda_bf16.h>
#include <cuda_fp16.h>
#include <math.h>
#include <stdint.h>

#define BBATCH 2
#define TT 2048
#define CC 1024
#define HH 16
#define C3 3072
#define MTOT 4096
#define KP 512          // k-pairs (1024/2)

// ---------------------------------------------------------------------------
// Scratch (__device__ globals; no allocation allowed)
// ---------------------------------------------------------------------------
__device__ float    g_q [(size_t)MTOT * CC];             // fp32 Q (QKV epilogue)
__device__ uint32_t g_KH[(size_t)BBATCH*HH*TT*32];       // K bf16-hi packed [b,h,key,dp]
__device__ uint32_t g_KL[(size_t)BBATCH*HH*TT*32];       // K bf16-lo packed
__device__ uint16_t g_V [(size_t)BBATCH*HH*TT*64];       // V fp16, [b,h,keypair,d]{key&1}
__device__ uint32_t g_XH[(size_t)MTOT*KP];               // x split, A-plane layout
__device__ uint32_t g_XL[(size_t)MTOT*KP];
__device__ uint32_t g_WQh[(size_t)KP*C3];                // W_qkv split, B-plane layout
__device__ uint32_t g_WQl[(size_t)KP*C3];
__device__ uint32_t g_WOh[(size_t)KP*CC];                // W_out split
__device__ uint32_t g_WOl[(size_t)KP*CC];
__device__ uint32_t g_ATh[(size_t)MTOT*KP];              // attention out split (A-plane)
__device__ uint32_t g_ATl[(size_t)MTOT*KP];

// ---------------------------------------------------------------------------
// helpers
// ---------------------------------------------------------------------------
__device__ __forceinline__ void bsplit(float x, uint16_t& h, uint16_t& l) {
    __nv_bfloat16 hb = __float2bfloat16_rn(x);
    float hf = __bfloat162float(hb);
    __nv_bfloat16 lb = __float2bfloat16_rn(x - hf);
    h = __bfloat16_as_ushort(hb);
    l = __bfloat16_as_ushort(lb);
}
__device__ __forceinline__ uint32_t pk(uint16_t a, uint16_t b) {
    return (uint32_t)a | ((uint32_t)b << 16);
}
__device__ __forceinline__ void split_pk2(float x0, float x1, uint32_t& hi, uint32_t& lo) {
    uint16_t h0, l0, h1, l1;
    bsplit(x0, h0, l0); bsplit(x1, h1, l1);
    hi = pk(h0, h1); lo = pk(l0, l1);
}
__device__ __forceinline__ uint32_t sptr(const void* p) {
    return (uint32_t)__cvta_generic_to_shared(p);
}
__device__ __forceinline__ void ldm4(uint32_t* r, uint32_t addr) {
    asm volatile("ldmatrix.sync.aligned.m8n8.x4.shared.b16 {%0,%1,%2,%3}, [%4];"
        : "=r"(r[0]), "=r"(r[1]), "=r"(r[2]), "=r"(r[3]) : "r"(addr));
}
#define CP16(dst, src) \
    asm volatile("cp.async.cg.shared.global [%0], [%1], 16;\n" :: "r"(dst), "l"(src))
#define CP_COMMIT() asm volatile("cp.async.commit_group;\n")
#define CP_WAIT_ALL() asm volatile("cp.async.wait_group 0;\n")

__device__ __forceinline__ void mma16(float* d, const uint32_t* a,
                                      uint32_t b0, uint32_t b1) {
    asm volatile(
        "mma.sync.aligned.m16n8k16.row.col.f32.bf16.bf16.f32 "
        "{%0,%1,%2,%3}, {%4,%5,%6,%7}, {%8,%9}, {%0,%1,%2,%3};\n"
        : "+f"(d[0]), "+f"(d[1]), "+f"(d[2]), "+f"(d[3])
        : "r"(a[0]), "r"(a[1]), "r"(a[2]), "r"(a[3]), "r"(b0), "r"(b1));
}
__device__ __forceinline__ void mma16h(float* d, const uint32_t* a,
                                       uint32_t b0, uint32_t b1) {
    asm volatile(
        "mma.sync.aligned.m16n8k16.row.col.f32.f16.f16.f32 "
        "{%0,%1,%2,%3}, {%4,%5,%6,%7}, {%8,%9}, {%0,%1,%2,%3};\n"
        : "+f"(d[0]), "+f"(d[1]), "+f"(d[2]), "+f"(d[3])
        : "r"(a[0]), "r"(a[1]), "r"(a[2]), "r"(a[3]), "r"(b0), "r"(b1));
}

// ---------------------------------------------------------------------------
// Prep kernels
// ---------------------------------------------------------------------------
__global__ void split_A_kernel(const float* __restrict__ src,
                               uint32_t* __restrict__ hi, uint32_t* __restrict__ lo,
                               int nquads) {
    int i = blockIdx.x * blockDim.x + threadIdx.x;
    if (i >= nquads) return;
    float4 v = ((const float4*)src)[i];
    uint32_t h0, l0, h1, l1;
    split_pk2(v.x, v.y, h0, l0);
    split_pk2(v.z, v.w, h1, l1);
    ((uint2*)hi)[i] = make_uint2(h0, h1);
    ((uint2*)lo)[i] = make_uint2(l0, l1);
}
__global__ void split_B_kernel(const float* __restrict__ W,
                               uint32_t* __restrict__ hi, uint32_t* __restrict__ lo,
                               int N) {
    int i = blockIdx.x * blockDim.x + threadIdx.x;
    int nq = N >> 2;
    if (i >= KP * nq) return;
    int kp = i / nq, c4 = (i - kp * nq) * 4;
    const float* p0 = W + (size_t)(2 * kp) * N + c4;
    float4 r0 = *(const float4*)p0;
    float4 r1 = *(const float4*)(p0 + N);
    uint16_t a, b, c, d;
    uint4 hv, lv;
    bsplit(r0.x, a, c); bsplit(r1.x, b, d); hv.x = pk(a, b); lv.x = pk(c, d);
    bsplit(r0.y, a, c); bsplit(r1.y, b, d); hv.y = pk(a, b); lv.y = pk(c, d);
    bsplit(r0.z, a, c); bsplit(r1.z, b, d); hv.z = pk(a, b); lv.z = pk(c, d);
    bsplit(r0.w, a, c); bsplit(r1.w, b, d); hv.w = pk(a, b); lv.w = pk(c, d);
    *(uint4*)(hi + (size_t)kp * N + c4) = hv;
    *(uint4*)(lo + (size_t)kp * N + c4) = lv;
}

// ---------------------------------------------------------------------------
// GEMM: pre-split bf16x3, cp.async double-buffer, ldmatrix A frags.
// BM=BN=128, BK=32 (16 kpairs), 256 threads (8 warps 2x4, warp tile 64x32).
// EPI 0: fp32 C + bias.  EPI 1: QKV epilogue (Q fp32 / K split bf16 / V fp16).
// ---------------------------------------------------------------------------
#define ASTG (128*20)
#define BSTG (16*136)
#define GEMM_SMEM_BYTES ((4*ASTG + 4*BSTG) * 4)   // 75776

template<int EPI>
__global__ void __launch_bounds__(256, 2)
gemm_sp(const uint32_t* __restrict__ Aph, const uint32_t* __restrict__ Apl,
        const uint32_t* __restrict__ Bph, const uint32_t* __restrict__ Bpl,
        const float* __restrict__ bias, float* __restrict__ Cout, int N) {
    extern __shared__ uint32_t smg[];
    uint32_t* sAh = smg;
    uint32_t* sAl = smg + 2 * ASTG;
    uint32_t* sBh = smg + 4 * ASTG;
    uint32_t* sBl = smg + 4 * ASTG + 2 * BSTG;

    const int tid = threadIdx.x;
    const int lane = tid & 31, wid = tid >> 5;
    const int g = lane >> 2, t = lane & 3;
    const int wm = (wid >> 2) * 64, wn = (wid & 3) * 32;
    const int bx = blockIdx.x, by = blockIdx.y;

    float acc[4][4][4];
#pragma unroll
    for (int i = 0; i < 4; i++)
#pragma unroll
        for (int j = 0; j < 4; j++)
#pragma unroll
            for (int r = 0; r < 4; r++) acc[i][j][r] = 0.0f;

    auto load_stage = [&](int st, int kp0) {
#pragma unroll
        for (int i = 0; i < 2; i++) {
            int id = tid + i * 256;
            int row = id >> 2, c = (id & 3) * 4;
            size_t go = (size_t)(by * 128 + row) * KP + kp0 + c;
            CP16(sptr(&sAh[st * ASTG + row * 20 + c]), Aph + go);
            CP16(sptr(&sAl[st * ASTG + row * 20 + c]), Apl + go);
        }
#pragma unroll
        for (int i = 0; i < 2; i++) {
            int id = tid + i * 256;
            int row = id >> 5, c = (id & 31) * 4;
            size_t go = (size_t)(kp0 + row) * N + bx * 128 + c;
            CP16(sptr(&sBh[st * BSTG + row * 136 + c]), Bph + go);
            CP16(sptr(&sBl[st * BSTG + row * 136 + c]), Bpl + go);
        }
    };

    load_stage(0, 0);
    CP_COMMIT();

    const int NK = KP / 16;   // 32
    const int arow = lane & 15;
    const int ahalf = (lane >> 4) * 4;

    for (int k = 0; k < NK; k++) {
        int st = k & 1;
        CP_WAIT_ALL();
        __syncthreads();
        if (k + 1 < NK) load_stage(st ^ 1, (k + 1) * 16);
        CP_COMMIT();

#pragma unroll
        for (int s = 0; s < 2; s++) {
            const int acol = s * 8 + ahalf;
            uint32_t af[4][4], bf[4][2];
#pragma unroll
            for (int mt = 0; mt < 4; mt++)
                ldm4(af[mt], sptr(&sAl[st * ASTG + (wm + mt * 16 + arow) * 20 + acol]));
#pragma unroll
            for (int nt = 0; nt < 4; nt++) {
                bf[nt][0] = sBh[st * BSTG + (s * 8 + t) * 136 + wn + nt * 8 + g];
                bf[nt][1] = sBh[st * BSTG + (s * 8 + t + 4) * 136 + wn + nt * 8 + g];
            }
#pragma unroll
            for (int mt = 0; mt < 4; mt++)
#pragma unroll
                for (int nt = 0; nt < 4; nt++)
                    mma16(acc[mt][nt], af[mt], bf[nt][0], bf[nt][1]);
#pragma unroll
            for (int mt = 0; mt < 4; mt++)
                ldm4(af[mt], sptr(&sAh[st * ASTG + (wm + mt * 16 + arow) * 20 + acol]));
#pragma unroll
            for (int mt = 0; mt < 4; mt++)
#pragma unroll
                for (int nt = 0; nt < 4; nt++)
                    mma16(acc[mt][nt], af[mt], bf[nt][0], bf[nt][1]);
#pragma unroll
            for (int nt = 0; nt < 4; nt++) {
                bf[nt][0] = sBl[st * BSTG + (s * 8 + t) * 136 + wn + nt * 8 + g];
                bf[nt][1] = sBl[st * BSTG + (s * 8 + t + 4) * 136 + wn + nt * 8 + g];
            }
#pragma unroll
            for (int mt = 0; mt < 4; mt++)
#pragma unroll
                for (int nt = 0; nt < 4; nt++)
                    mma16(acc[mt][nt], af[mt], bf[nt][0], bf[nt][1]);
        }
    }

    // ---------------- epilogue ----------------
#pragma unroll
    for (int mt = 0; mt < 4; mt++) {
        int row = by * 128 + wm + mt * 16 + g;
#pragma unroll
        for (int nt = 0; nt < 4; nt++) {
            int col = bx * 128 + wn + nt * 8 + 2 * t;
            float b0v = bias[col], b1v = bias[col + 1];
            float v0 = acc[mt][nt][0] + b0v, v1 = acc[mt][nt][1] + b1v;
            float v2 = acc[mt][nt][2] + b0v, v3 = acc[mt][nt][3] + b1v;
            if (EPI == 0) {
                *(float2*)&Cout[(size_t)row * N + col]       = make_float2(v0, v1);
                *(float2*)&Cout[(size_t)(row + 8) * N + col] = make_float2(v2, v3);
            } else {
                int region = bx >> 3;   // uniform per block: 0=Q, 1=K, 2=V
                int b = row >> 11, key = row & (TT - 1);
                if (region == 0) {
                    *(float2*)&g_q[(size_t)row * CC + col]       = make_float2(v0, v1);
                    *(float2*)&g_q[(size_t)(row + 8) * CC + col] = make_float2(v2, v3);
                } else if (region == 1) {
                    int c2 = col - CC;
                    int h = c2 >> 6, dp = (c2 & 63) >> 1;
                    size_t r0 = ((size_t)(b * HH + h) * TT + key) * 32 + dp;
                    size_t r1 = r0 + 8 * 32;
                    uint32_t hh, ll;
                    split_pk2(v0, v1, hh, ll); g_KH[r0] = hh; g_KL[r0] = ll;
                    split_pk2(v2, v3, hh, ll); g_KH[r1] = hh; g_KL[r1] = ll;
                } else {
                    // V fp16, key-pair packed: u16 idx = (wbase + d)*2 + (key&1)
                    int c2 = col - 2 * CC;
                    int h = c2 >> 6, d = c2 & 63;
                    size_t wbase = ((size_t)(b * HH + h) * (TT >> 1) + (key >> 1)) * 64;
                    int par = key & 1;
                    g_V[(wbase + d)     * 2 + par] = __half_as_ushort(__float2half_rn(v0));
                    g_V[(wbase + d + 1) * 2 + par] = __half_as_ushort(__float2half_rn(v1));
                    size_t wbase8 = wbase + 4 * 64;   // key+8 -> kpair+4
                    g_V[(wbase8 + d)     * 2 + par] = __half_as_ushort(__float2half_rn(v2));
                    g_V[(wbase8 + d + 1) * 2 + par] = __half_as_ushort(__float2half_rn(v3));
                }
            }
        }
    }
}

// ---------------------------------------------------------------------------
// Flash attention: 256 threads (8 warps), q-tile 128, K/V tile 64,
// cp.async double-buffer, ldmatrix K frags, bf16x3 scores, fp16 P*V.
// grid (T/128, H, B).
// ---------------------------------------------------------------------------
#define KSTG (64*36)            // u32 per K stage per plane
#define VSTG (32*72)            // u32 per V stage (32 keypairs x 64 d, stride 72)
#define PS_STRIDE 36            // u32 (half2) per P row
#define ATTN_SMEM_WORDS (4*KSTG + 2*VSTG + 8*16*PS_STRIDE)   // 18432
#define ATTN_SMEM_BYTES (ATTN_SMEM_WORDS * 4)                // 73728

__global__ void __launch_bounds__(256, 2)
attn_sp() {
    extern __shared__ uint32_t sma[];
    uint32_t* sKh = sma;                             // [2][64][36] bf16-hi pairs
    uint32_t* sKl = sma + 2 * KSTG;                  // [2][64][36] bf16-lo pairs
    uint32_t* sVp = sma + 4 * KSTG;                  // [2][32][72] fp16 keypair x d
    uint32_t* sP  = sma + 4 * KSTG + 2 * VSTG;       // [8][16][36] half2 P

    const int tid = threadIdx.x;
    const int lane = tid & 31, wid = tid >> 5;
    const int g = lane >> 2, t = lane & 3;
    const int qt = blockIdx.x, h = blockIdx.y, b = blockIdx.z;
    const int bh = b * HH + h;
    const uint32_t* KHb = g_KH + (size_t)bh * TT * 32;
    const uint32_t* KLb = g_KL + (size_t)bh * TT * 32;
    const uint32_t* Vbp = (const uint32_t*)g_V + (size_t)bh * (TT >> 1) * 64;

    const int q0 = qt * 128 + wid * 16;
    const int grow = b * TT + q0;

    // Q fragments (bf16 hi/lo packed pairs), scaled 1/8, loaded once.
    uint32_t qh[4][4], ql[4][4];
    {
        const float* qr0 = g_q + (size_t)(grow + g) * CC + h * 64;
        const float* qr1 = g_q + (size_t)(grow + g + 8) * CC + h * 64;
#pragma unroll
        for (int s = 0; s < 4; s++) {
            int p0 = s * 8 + t, p1 = s * 8 + t + 4;
            split_pk2(qr0[2*p0] * 0.125f, qr0[2*p0+1] * 0.125f, qh[s][0], ql[s][0]);
            split_pk2(qr1[2*p0] * 0.125f, qr1[2*p0+1] * 0.125f, qh[s][1], ql[s][1]);
            split_pk2(qr0[2*p1] * 0.125f, qr0[2*p1+1] * 0.125f, qh[s][2], ql[s][2]);
            split_pk2(qr1[2*p1] * 0.125f, qr1[2*p1+1] * 0.125f, qh[s][3], ql[s][3]);
        }
    }

    float mrow0 = -INFINITY, mrow1 = -INFINITY;
    float lrow0 = 0.0f, lrow1 = 0.0f;
    float oacc[8][4];
#pragma unroll
    for (int nt = 0; nt < 8; nt++)
#pragma unroll
        for (int r = 0; r < 4; r++) oacc[nt][r] = 0.0f;

    uint32_t* Pw = sP + wid * 16 * PS_STRIDE;

    auto load_tile = [&](int st, int kt) {
#pragma unroll
        for (int i = 0; i < 2; i++) {
            int id = tid + i * 256;
            int row = id >> 3, c = (id & 7) * 4;
            size_t go = (size_t)(kt + row) * 32 + c;
            CP16(sptr(&sKh[st * KSTG + row * 36 + c]), KHb + go);
            CP16(sptr(&sKl[st * KSTG + row * 36 + c]), KLb + go);
        }
        // V: 32 keypairs x 64 u32 = 512 x 16B, 2 per thread
#pragma unroll
        for (int i = 0; i < 2; i++) {
            int id = tid + i * 256;
            int row = id >> 4, c = (id & 15) * 4;
            CP16(sptr(&sVp[st * VSTG + row * 72 + c]),
                 Vbp + (size_t)((kt >> 1) + row) * 64 + c);
        }
    };

    load_tile(0, 0);
    CP_COMMIT();

    const int krow = lane & 15;
    const int khalf = (lane >> 4) * 4;

    for (int kti = 0; kti < TT / 64; kti++) {
        int st = kti & 1;
        CP_WAIT_ALL();
        __syncthreads();
        if (kti + 1 < TT / 64) load_tile(st ^ 1, (kti + 1) * 64);
        CP_COMMIT();

        // S = Q K^T  (bf16x3) — ldmatrix K frags
        float sacc[8][4];
#pragma unroll
        for (int nt = 0; nt < 8; nt++)
#pragma unroll
            for (int r = 0; r < 4; r++) sacc[nt][r] = 0.0f;

#pragma unroll
        for (int npp = 0; npp < 4; npp++) {
            const int kb = npp * 16;
#pragma unroll
            for (int s = 0; s < 4; s++) {
                uint32_t kf[4];
                ldm4(kf, sptr(&sKh[st * KSTG + (kb + krow) * 36 + s * 8 + khalf]));
                mma16(sacc[2*npp],     ql[s], kf[0], kf[2]);
                mma16(sacc[2*npp + 1], ql[s], kf[1], kf[3]);
                mma16(sacc[2*npp],     qh[s], kf[0], kf[2]);
                mma16(sacc[2*npp + 1], qh[s], kf[1], kf[3]);
                ldm4(kf, sptr(&sKl[st * KSTG + (kb + krow) * 36 + s * 8 + khalf]));
                mma16(sacc[2*npp],     qh[s], kf[0], kf[2]);
                mma16(sacc[2*npp + 1], qh[s], kf[1], kf[3]);
            }
        }

        // Online softmax
        float mx0 = -INFINITY, mx1 = -INFINITY;
#pragma unroll
        for (int nt = 0; nt < 8; nt++) {
            mx0 = fmaxf(mx0, fmaxf(sacc[nt][0], sacc[nt][1]));
            mx1 = fmaxf(mx1, fmaxf(sacc[nt][2], sacc[nt][3]));
        }
        mx0 = fmaxf(mx0, __shfl_xor_sync(0xffffffffu, mx0, 1));
        mx0 = fmaxf(mx0, __shfl_xor_sync(0xffffffffu, mx0, 2));
        mx1 = fmaxf(mx1, __shfl_xor_sync(0xffffffffu, mx1, 1));
        mx1 = fmaxf(mx1, __shfl_xor_sync(0xffffffffu, mx1, 2));

        float mn0 = fmaxf(mrow0, mx0);
        float mn1 = fmaxf(mrow1, mx1);
        float c0 = __expf(mrow0 - mn0);
        float c1 = __expf(mrow1 - mn1);
        lrow0 *= c0; lrow1 *= c1;
#pragma unroll
        for (int nt = 0; nt < 8; nt++) {
            oacc[nt][0] *= c0; oacc[nt][1] *= c0;
            oacc[nt][2] *= c1; oacc[nt][3] *= c1;
        }

        // P = exp(S - m), rounded to fp16 (consistent with l-sum)
        float s0 = 0.0f, s1 = 0.0f;
#pragma unroll
        for (int nt = 0; nt < 8; nt++) {
            __half2 H0 = __float22half2_rn(make_float2(__expf(sacc[nt][0] - mn0),
                                                       __expf(sacc[nt][1] - mn0)));
            __half2 H1 = __float22half2_rn(make_float2(__expf(sacc[nt][2] - mn1),
                                                       __expf(sacc[nt][3] - mn1)));
            float2 f0 = __half22float2(H0);
            float2 f1 = __half22float2(H1);
            s0 += f0.x + f0.y;
            s1 += f1.x + f1.y;
            Pw[(g    ) * PS_STRIDE + nt * 4 + t] = *(uint32_t*)&H0;
            Pw[(g + 8) * PS_STRIDE + nt * 4 + t] = *(uint32_t*)&H1;
        }
        s0 += __shfl_xor_sync(0xffffffffu, s0, 1);
        s0 += __shfl_xor_sync(0xffffffffu, s0, 2);
        s1 += __shfl_xor_sync(0xffffffffu, s1, 1);
        s1 += __shfl_xor_sync(0xffffffffu, s1, 2);
        lrow0 += s0; lrow1 += s1;
        mrow0 = mn0; mrow1 = mn1;

        __syncwarp();

        // O += P V   (fp16 m16n8k16): 4 k16 steps cover 64 keys
        const uint32_t* Vst = sVp + st * VSTG;
#pragma unroll
        for (int s = 0; s < 4; s++) {
            uint32_t pa[4];
            pa[0] = Pw[(g    ) * PS_STRIDE + s * 8 + t];
            pa[1] = Pw[(g + 8) * PS_STRIDE + s * 8 + t];
            pa[2] = Pw[(g    ) * PS_STRIDE + s * 8 + 4 + t];
            pa[3] = Pw[(g + 8) * PS_STRIDE + s * 8 + 4 + t];
#pragma unroll
            for (int nt = 0; nt < 8; nt++) {
                uint32_t b0 = Vst[(s * 8 + t    ) * 72 + nt * 8 + g];
                uint32_t b1 = Vst[(s * 8 + 4 + t) * 72 + nt * 8 + g];
                mma16h(oacc[nt], pa, b0, b1);
            }
        }
    }

    // Epilogue: normalize, write split bf16 planes (A-layout for out-proj)
    const float inv0 = 1.0f / lrow0;
    const float inv1 = 1.0f / lrow1;
    const size_t r0 = (size_t)(grow + g) * KP;
    const size_t r1 = (size_t)(grow + g + 8) * KP;
#pragma unroll
    for (int nt = 0; nt < 8; nt++) {
        int kp = h * 32 + nt * 4 + t;
        uint32_t hh, ll;
        split_pk2(oacc[nt][0] * inv0, oacc[nt][1] * inv0, hh, ll);
        g_ATh[r0 + kp] = hh; g_ATl[r0 + kp] = ll;
        split_pk2(oacc[nt][2] * inv1, oacc[nt][3] * inv1, hh, ll);
        g_ATh[r1 + kp] = hh; g_ATl[r1 + kp] = ll;
    }
}

// ---------------------------------------------------------------------------
// Launch
// ---------------------------------------------------------------------------
extern "C" void kernel_launch(void* const* d_in, const int* in_sizes, int n_in,
                              void* d_out, int out_size) {
    const float* x    = (const float*)d_in[0];
    const float* Wqkv = (const float*)d_in[1];
    const float* bqkv = (const float*)d_in[2];
    const float* Wout = (const float*)d_in[3];
    const float* bout = (const float*)d_in[4];
    float* out = (float*)d_out;

    uint32_t *XH, *XL, *WQh, *WQl, *WOh, *WOl, *ATh, *ATl;
    cudaGetSymbolAddress((void**)&XH,  g_XH);
    cudaGetSymbolAddress((void**)&XL,  g_XL);
    cudaGetSymbolAddress((void**)&WQh, g_WQh);
    cudaGetSymbolAddress((void**)&WQl, g_WQl);
    cudaGetSymbolAddress((void**)&WOh, g_WOh);
    cudaGetSymbolAddress((void**)&WOl, g_WOl);
    cudaGetSymbolAddress((void**)&ATh, g_ATh);
    cudaGetSymbolAddress((void**)&ATl, g_ATl);

    cudaFuncSetAttribute(gemm_sp<0>, cudaFuncAttributeMaxDynamicSharedMemorySize,
                         GEMM_SMEM_BYTES);
    cudaFuncSetAttribute(gemm_sp<1>, cudaFuncAttributeMaxDynamicSharedMemorySize,
                         GEMM_SMEM_BYTES);
    cudaFuncSetAttribute(attn_sp, cudaFuncAttributeMaxDynamicSharedMemorySize,
                         ATTN_SMEM_BYTES);

    // Prep: split x and weights
    {
        int nq = MTOT * CC / 4;
        split_A_kernel<<<(nq + 255) / 256, 256>>>(x, XH, XL, nq);
    }
    split_B_kernel<<<(KP * (C3 / 4) + 255) / 256, 256>>>(Wqkv, WQh, WQl, C3);
    split_B_kernel<<<(KP * (CC / 4) + 255) / 256, 256>>>(Wout, WOh, WOl, CC);

    // 1) QKV projection with fused Q/K/V-layout epilogue
    gemm_sp<1><<<dim3(C3 / 128, MTOT / 128), 256, GEMM_SMEM_BYTES>>>(
        XH, XL, WQh, WQl, bqkv, nullptr, C3);

    // 2) Flash attention
    attn_sp<<<dim3(TT / 128, HH, BBATCH), 256, ATTN_SMEM_BYTES>>>();

    // 3) Output projection
    gemm_sp<0><<<dim3(CC / 128, MTOT / 128), 256, GEMM_SMEM_BYTES>>>(
        ATh, ATl, WOh, WOl, bout, out, CC);
}

// round 11
// speedup vs baseline: 1.4733x; 1.2955x over previous
#include <cuda_runtime.h>
#include <cuda_fp16.h>
#include <math.h>
#include <stdint.h>

#define BBATCH 2
#define TT 2048
#define CC 1024
#define HH 16
#define C3 3072
#define MTOT 4096
#define KP 512          // k-pairs (1024/2)

// ---------------------------------------------------------------------------
// Scratch (__device__ globals; no allocation allowed)
// ---------------------------------------------------------------------------
__device__ float    g_q [(size_t)MTOT * CC];             // fp32 Q (QKV epilogue)
__device__ uint32_t g_K [(size_t)BBATCH*HH*TT*32];       // K fp16 packed [b,h,key,dp]
__device__ uint16_t g_V [(size_t)BBATCH*HH*TT*64];       // V fp16, [b,h,keypair,d]{key&1}
__device__ uint32_t g_XH[(size_t)MTOT*KP];               // x fp16-hi pairs (A-plane)
__device__ uint32_t g_XL[(size_t)MTOT*KP];               // x fp16-lo pairs
__device__ uint32_t g_WQ[(size_t)KP*C3];                 // W_qkv fp16 pairs (B-plane)
__device__ uint32_t g_WO[(size_t)KP*CC];                 // W_out fp16 pairs
__device__ uint32_t g_ATh[(size_t)MTOT*KP];              // attn out fp16-hi (A-plane)
__device__ uint32_t g_ATl[(size_t)MTOT*KP];              // attn out fp16-lo

// ---------------------------------------------------------------------------
// helpers
// ---------------------------------------------------------------------------
__device__ __forceinline__ uint16_t h16(float x) {
    return __half_as_ushort(__float2half_rn(x));
}
__device__ __forceinline__ void hsplit(float x, uint16_t& h, uint16_t& l) {
    __half hb = __float2half_rn(x);
    h = __half_as_ushort(hb);
    l = h16(x - __half2float(hb));
}
__device__ __forceinline__ uint32_t pk(uint16_t a, uint16_t b) {
    return (uint32_t)a | ((uint32_t)b << 16);
}
__device__ __forceinline__ void hsplit_pk2(float x0, float x1,
                                           uint32_t& hi, uint32_t& lo) {
    uint16_t h0, l0, h1, l1;
    hsplit(x0, h0, l0); hsplit(x1, h1, l1);
    hi = pk(h0, h1); lo = pk(l0, l1);
}
__device__ __forceinline__ uint32_t sptr(const void* p) {
    return (uint32_t)__cvta_generic_to_shared(p);
}
__device__ __forceinline__ void ldm4(uint32_t* r, uint32_t addr) {
    asm volatile("ldmatrix.sync.aligned.m8n8.x4.shared.b16 {%0,%1,%2,%3}, [%4];"
        : "=r"(r[0]), "=r"(r[1]), "=r"(r[2]), "=r"(r[3]) : "r"(addr));
}
#define CP16(dst, src) \
    asm volatile("cp.async.cg.shared.global [%0], [%1], 16;\n" :: "r"(dst), "l"(src))
#define CP_COMMIT() asm volatile("cp.async.commit_group;\n")
#define CP_WAIT_ALL() asm volatile("cp.async.wait_group 0;\n")

__device__ __forceinline__ void mma16h(float* d, const uint32_t* a,
                                       uint32_t b0, uint32_t b1) {
    asm volatile(
        "mma.sync.aligned.m16n8k16.row.col.f32.f16.f16.f32 "
        "{%0,%1,%2,%3}, {%4,%5,%6,%7}, {%8,%9}, {%0,%1,%2,%3};\n"
        : "+f"(d[0]), "+f"(d[1]), "+f"(d[2]), "+f"(d[3])
        : "r"(a[0]), "r"(a[1]), "r"(a[2]), "r"(a[3]), "r"(b0), "r"(b1));
}

// ---------------------------------------------------------------------------
// Prep kernels
// ---------------------------------------------------------------------------
__global__ void split_A_kernel(const float* __restrict__ src,
                               uint32_t* __restrict__ hi, uint32_t* __restrict__ lo,
                               int nquads) {
    int i = blockIdx.x * blockDim.x + threadIdx.x;
    if (i >= nquads) return;
    float4 v = ((const float4*)src)[i];
    uint32_t h0, l0, h1, l1;
    hsplit_pk2(v.x, v.y, h0, l0);
    hsplit_pk2(v.z, v.w, h1, l1);
    ((uint2*)hi)[i] = make_uint2(h0, h1);
    ((uint2*)lo)[i] = make_uint2(l0, l1);
}
// W[K][N] -> single fp16 B-plane: Wp[kp][n] = pk(h16(W[2kp][n]), h16(W[2kp+1][n]))
__global__ void split_Bh_kernel(const float* __restrict__ W,
                                uint32_t* __restrict__ hi, int N) {
    int i = blockIdx.x * blockDim.x + threadIdx.x;
    int nq = N >> 2;
    if (i >= KP * nq) return;
    int kp = i / nq, c4 = (i - kp * nq) * 4;
    const float* p0 = W + (size_t)(2 * kp) * N + c4;
    float4 r0 = *(const float4*)p0;
    float4 r1 = *(const float4*)(p0 + N);
    uint4 hv;
    hv.x = pk(h16(r0.x), h16(r1.x));
    hv.y = pk(h16(r0.y), h16(r1.y));
    hv.z = pk(h16(r0.z), h16(r1.z));
    hv.w = pk(h16(r0.w), h16(r1.w));
    *(uint4*)(hi + (size_t)kp * N + c4) = hv;
}

// ---------------------------------------------------------------------------
// GEMM (fp16x2, one-sided split): C = (Ah+Al) @ Bh16 + bias
// BM=BN=128, BK=32 (16 kpairs), 256 threads (8 warps 2x4, warp tile 64x32).
// EPI 0: fp32 C + bias.  EPI 1: QKV epilogue (Q fp32 / K fp16 / V fp16).
// ---------------------------------------------------------------------------
#define ASTG (128*20)
#define BSTG (16*136)
#define GEMM_SMEM_BYTES ((4*ASTG + 2*BSTG) * 4)   // 58368

template<int EPI>
__global__ void __launch_bounds__(256, 2)
gemm_sp(const uint32_t* __restrict__ Aph, const uint32_t* __restrict__ Apl,
        const uint32_t* __restrict__ Bp,
        const float* __restrict__ bias, float* __restrict__ Cout, int N) {
    extern __shared__ uint32_t smg[];
    uint32_t* sAh = smg;
    uint32_t* sAl = smg + 2 * ASTG;
    uint32_t* sBh = smg + 4 * ASTG;

    const int tid = threadIdx.x;
    const int lane = tid & 31, wid = tid >> 5;
    const int g = lane >> 2, t = lane & 3;
    const int wm = (wid >> 2) * 64, wn = (wid & 3) * 32;
    const int bx = blockIdx.x, by = blockIdx.y;

    float acc[4][4][4];
#pragma unroll
    for (int i = 0; i < 4; i++)
#pragma unroll
        for (int j = 0; j < 4; j++)
#pragma unroll
            for (int r = 0; r < 4; r++) acc[i][j][r] = 0.0f;

    auto load_stage = [&](int st, int kp0) {
#pragma unroll
        for (int i = 0; i < 2; i++) {
            int id = tid + i * 256;
            int row = id >> 2, c = (id & 3) * 4;
            size_t go = (size_t)(by * 128 + row) * KP + kp0 + c;
            CP16(sptr(&sAh[st * ASTG + row * 20 + c]), Aph + go);
            CP16(sptr(&sAl[st * ASTG + row * 20 + c]), Apl + go);
        }
#pragma unroll
        for (int i = 0; i < 2; i++) {
            int id = tid + i * 256;
            int row = id >> 5, c = (id & 31) * 4;
            size_t go = (size_t)(kp0 + row) * N + bx * 128 + c;
            CP16(sptr(&sBh[st * BSTG + row * 136 + c]), Bp + go);
        }
    };

    load_stage(0, 0);
    CP_COMMIT();

    const int NK = KP / 16;   // 32
    const int arow = lane & 15;
    const int ahalf = (lane >> 4) * 4;

    for (int k = 0; k < NK; k++) {
        int st = k & 1;
        CP_WAIT_ALL();
        __syncthreads();
        if (k + 1 < NK) load_stage(st ^ 1, (k + 1) * 16);
        CP_COMMIT();

#pragma unroll
        for (int s = 0; s < 2; s++) {
            const int acol = s * 8 + ahalf;
            uint32_t af[4][4], bf[4][2];
#pragma unroll
            for (int nt = 0; nt < 4; nt++) {
                bf[nt][0] = sBh[st * BSTG + (s * 8 + t) * 136 + wn + nt * 8 + g];
                bf[nt][1] = sBh[st * BSTG + (s * 8 + t + 4) * 136 + wn + nt * 8 + g];
            }
            // lo(A) x B
#pragma unroll
            for (int mt = 0; mt < 4; mt++)
                ldm4(af[mt], sptr(&sAl[st * ASTG + (wm + mt * 16 + arow) * 20 + acol]));
#pragma unroll
            for (int mt = 0; mt < 4; mt++)
#pragma unroll
                for (int nt = 0; nt < 4; nt++)
                    mma16h(acc[mt][nt], af[mt], bf[nt][0], bf[nt][1]);
            // hi(A) x B
#pragma unroll
            for (int mt = 0; mt < 4; mt++)
                ldm4(af[mt], sptr(&sAh[st * ASTG + (wm + mt * 16 + arow) * 20 + acol]));
#pragma unroll
            for (int mt = 0; mt < 4; mt++)
#pragma unroll
                for (int nt = 0; nt < 4; nt++)
                    mma16h(acc[mt][nt], af[mt], bf[nt][0], bf[nt][1]);
        }
    }

    // ---------------- epilogue ----------------
#pragma unroll
    for (int mt = 0; mt < 4; mt++) {
        int row = by * 128 + wm + mt * 16 + g;
#pragma unroll
        for (int nt = 0; nt < 4; nt++) {
            int col = bx * 128 + wn + nt * 8 + 2 * t;
            float b0v = bias[col], b1v = bias[col + 1];
            float v0 = acc[mt][nt][0] + b0v, v1 = acc[mt][nt][1] + b1v;
            float v2 = acc[mt][nt][2] + b0v, v3 = acc[mt][nt][3] + b1v;
            if (EPI == 0) {
                *(float2*)&Cout[(size_t)row * N + col]       = make_float2(v0, v1);
                *(float2*)&Cout[(size_t)(row + 8) * N + col] = make_float2(v2, v3);
            } else {
                int region = bx >> 3;   // uniform per block: 0=Q, 1=K, 2=V
                int b = row >> 11, key = row & (TT - 1);
                if (region == 0) {
                    *(float2*)&g_q[(size_t)row * CC + col]       = make_float2(v0, v1);
                    *(float2*)&g_q[(size_t)(row + 8) * CC + col] = make_float2(v2, v3);
                } else if (region == 1) {
                    int c2 = col - CC;
                    int h = c2 >> 6, dp = (c2 & 63) >> 1;
                    size_t r0 = ((size_t)(b * HH + h) * TT + key) * 32 + dp;
                    g_K[r0]          = pk(h16(v0), h16(v1));
                    g_K[r0 + 8 * 32] = pk(h16(v2), h16(v3));
                } else {
                    // V fp16, key-pair packed: u16 idx = (wbase + d)*2 + (key&1)
                    int c2 = col - 2 * CC;
                    int h = c2 >> 6, d = c2 & 63;
                    size_t wbase = ((size_t)(b * HH + h) * (TT >> 1) + (key >> 1)) * 64;
                    int par = key & 1;
                    g_V[(wbase + d)     * 2 + par] = h16(v0);
                    g_V[(wbase + d + 1) * 2 + par] = h16(v1);
                    size_t wbase8 = wbase + 4 * 64;   // key+8 -> kpair+4
                    g_V[(wbase8 + d)     * 2 + par] = h16(v2);
                    g_V[(wbase8 + d + 1) * 2 + par] = h16(v3);
                }
            }
        }
    }
}

// ---------------------------------------------------------------------------
// Flash attention: 256 threads (8 warps), q-tile 128, K/V tile 64,
// cp.async double-buffer, S = (Qh+Ql) K16 fp16x2, fp16 P*V.
// grid (T/128, H, B).
// ---------------------------------------------------------------------------
#define KSTG (64*36)            // u32 per K stage
#define VSTG (32*72)            // u32 per V stage (32 keypairs x 64 d)
#define PS_STRIDE 36
#define ATTN_SMEM_WORDS (2*KSTG + 2*VSTG + 8*16*PS_STRIDE)   // 13824
#define ATTN_SMEM_BYTES (ATTN_SMEM_WORDS * 4)                // 55296

__global__ void __launch_bounds__(256, 2)
attn_sp() {
    extern __shared__ uint32_t sma[];
    uint32_t* sKh = sma;                             // [2][64][36] fp16 pairs
    uint32_t* sVp = sma + 2 * KSTG;                  // [2][32][72] fp16 keypair x d
    uint32_t* sP  = sma + 2 * KSTG + 2 * VSTG;       // [8][16][36] half2 P

    const int tid = threadIdx.x;
    const int lane = tid & 31, wid = tid >> 5;
    const int g = lane >> 2, t = lane & 3;
    const int qt = blockIdx.x, h = blockIdx.y, b = blockIdx.z;
    const int bh = b * HH + h;
    const uint32_t* Kb  = g_K + (size_t)bh * TT * 32;
    const uint32_t* Vbp = (const uint32_t*)g_V + (size_t)bh * (TT >> 1) * 64;

    const int q0 = qt * 128 + wid * 16;
    const int grow = b * TT + q0;

    // Q fragments (fp16 hi/lo packed pairs), scaled 1/8, loaded once.
    uint32_t qh[4][4], ql[4][4];
    {
        const float* qr0 = g_q + (size_t)(grow + g) * CC + h * 64;
        const float* qr1 = g_q + (size_t)(grow + g + 8) * CC + h * 64;
#pragma unroll
        for (int s = 0; s < 4; s++) {
            int p0 = s * 8 + t, p1 = s * 8 + t + 4;
            hsplit_pk2(qr0[2*p0] * 0.125f, qr0[2*p0+1] * 0.125f, qh[s][0], ql[s][0]);
            hsplit_pk2(qr1[2*p0] * 0.125f, qr1[2*p0+1] * 0.125f, qh[s][1], ql[s][1]);
            hsplit_pk2(qr0[2*p1] * 0.125f, qr0[2*p1+1] * 0.125f, qh[s][2], ql[s][2]);
            hsplit_pk2(qr1[2*p1] * 0.125f, qr1[2*p1+1] * 0.125f, qh[s][3], ql[s][3]);
        }
    }

    float mrow0 = -INFINITY, mrow1 = -INFINITY;
    float lrow0 = 0.0f, lrow1 = 0.0f;
    float oacc[8][4];
#pragma unroll
    for (int nt = 0; nt < 8; nt++)
#pragma unroll
        for (int r = 0; r < 4; r++) oacc[nt][r] = 0.0f;

    uint32_t* Pw = sP + wid * 16 * PS_STRIDE;

    auto load_tile = [&](int st, int kt) {
#pragma unroll
        for (int i = 0; i < 2; i++) {
            int id = tid + i * 256;
            int row = id >> 3, c = (id & 7) * 4;
            CP16(sptr(&sKh[st * KSTG + row * 36 + c]), Kb + (size_t)(kt + row) * 32 + c);
        }
#pragma unroll
        for (int i = 0; i < 2; i++) {
            int id = tid + i * 256;
            int row = id >> 4, c = (id & 15) * 4;
            CP16(sptr(&sVp[st * VSTG + row * 72 + c]),
                 Vbp + (size_t)((kt >> 1) + row) * 64 + c);
        }
    };

    load_tile(0, 0);
    CP_COMMIT();

    const int krow = lane & 15;
    const int khalf = (lane >> 4) * 4;

    for (int kti = 0; kti < TT / 64; kti++) {
        int st = kti & 1;
        CP_WAIT_ALL();
        __syncthreads();
        if (kti + 1 < TT / 64) load_tile(st ^ 1, (kti + 1) * 64);
        CP_COMMIT();

        // S = Q K^T  (fp16x2, one-sided split) — ldmatrix K frags
        float sacc[8][4];
#pragma unroll
        for (int nt = 0; nt < 8; nt++)
#pragma unroll
            for (int r = 0; r < 4; r++) sacc[nt][r] = 0.0f;

#pragma unroll
        for (int npp = 0; npp < 4; npp++) {
            const int kb = npp * 16;
#pragma unroll
            for (int s = 0; s < 4; s++) {
                uint32_t kf[4];
                ldm4(kf, sptr(&sKh[st * KSTG + (kb + krow) * 36 + s * 8 + khalf]));
                mma16h(sacc[2*npp],     ql[s], kf[0], kf[2]);
                mma16h(sacc[2*npp + 1], ql[s], kf[1], kf[3]);
                mma16h(sacc[2*npp],     qh[s], kf[0], kf[2]);
                mma16h(sacc[2*npp + 1], qh[s], kf[1], kf[3]);
            }
        }

        // Online softmax
        float mx0 = -INFINITY, mx1 = -INFINITY;
#pragma unroll
        for (int nt = 0; nt < 8; nt++) {
            mx0 = fmaxf(mx0, fmaxf(sacc[nt][0], sacc[nt][1]));
            mx1 = fmaxf(mx1, fmaxf(sacc[nt][2], sacc[nt][3]));
        }
        mx0 = fmaxf(mx0, __shfl_xor_sync(0xffffffffu, mx0, 1));
        mx0 = fmaxf(mx0, __shfl_xor_sync(0xffffffffu, mx0, 2));
        mx1 = fmaxf(mx1, __shfl_xor_sync(0xffffffffu, mx1, 1));
        mx1 = fmaxf(mx1, __shfl_xor_sync(0xffffffffu, mx1, 2));

        float mn0 = fmaxf(mrow0, mx0);
        float mn1 = fmaxf(mrow1, mx1);
        float c0 = __expf(mrow0 - mn0);
        float c1 = __expf(mrow1 - mn1);
        lrow0 *= c0; lrow1 *= c1;
#pragma unroll
        for (int nt = 0; nt < 8; nt++) {
            oacc[nt][0] *= c0; oacc[nt][1] *= c0;
            oacc[nt][2] *= c1; oacc[nt][3] *= c1;
        }

        // P = exp(S - m), rounded to fp16 (consistent with l-sum)
        float s0 = 0.0f, s1 = 0.0f;
#pragma unroll
        for (int nt = 0; nt < 8; nt++) {
            __half2 H0 = __float22half2_rn(make_float2(__expf(sacc[nt][0] - mn0),
                                                       __expf(sacc[nt][1] - mn0)));
            __half2 H1 = __float22half2_rn(make_float2(__expf(sacc[nt][2] - mn1),
                                                       __expf(sacc[nt][3] - mn1)));
            float2 f0 = __half22float2(H0);
            float2 f1 = __half22float2(H1);
            s0 += f0.x + f0.y;
            s1 += f1.x + f1.y;
            Pw[(g    ) * PS_STRIDE + nt * 4 + t] = *(uint32_t*)&H0;
            Pw[(g + 8) * PS_STRIDE + nt * 4 + t] = *(uint32_t*)&H1;
        }
        s0 += __shfl_xor_sync(0xffffffffu, s0, 1);
        s0 += __shfl_xor_sync(0xffffffffu, s0, 2);
        s1 += __shfl_xor_sync(0xffffffffu, s1, 1);
        s1 += __shfl_xor_sync(0xffffffffu, s1, 2);
        lrow0 += s0; lrow1 += s1;
        mrow0 = mn0; mrow1 = mn1;

        __syncwarp();

        // O += P V   (fp16 m16n8k16): 4 k16 steps cover 64 keys
        const uint32_t* Vst = sVp + st * VSTG;
#pragma unroll
        for (int s = 0; s < 4; s++) {
            uint32_t pa[4];
            pa[0] = Pw[(g    ) * PS_STRIDE + s * 8 + t];
            pa[1] = Pw[(g + 8) * PS_STRIDE + s * 8 + t];
            pa[2] = Pw[(g    ) * PS_STRIDE + s * 8 + 4 + t];
            pa[3] = Pw[(g + 8) * PS_STRIDE + s * 8 + 4 + t];
#pragma unroll
            for (int nt = 0; nt < 8; nt++) {
                uint32_t b0 = Vst[(s * 8 + t    ) * 72 + nt * 8 + g];
                uint32_t b1 = Vst[(s * 8 + 4 + t) * 72 + nt * 8 + g];
                mma16h(oacc[nt], pa, b0, b1);
            }
        }
    }

    // Epilogue: normalize, write fp16 hi/lo planes (A-layout for out-proj)
    const float inv0 = 1.0f / lrow0;
    const float inv1 = 1.0f / lrow1;
    const size_t r0 = (size_t)(grow + g) * KP;
    const size_t r1 = (size_t)(grow + g + 8) * KP;
#pragma unroll
    for (int nt = 0; nt < 8; nt++) {
        int kp = h * 32 + nt * 4 + t;
        uint32_t hh, ll;
        hsplit_pk2(oacc[nt][0] * inv0, oacc[nt][1] * inv0, hh, ll);
        g_ATh[r0 + kp] = hh; g_ATl[r0 + kp] = ll;
        hsplit_pk2(oacc[nt][2] * inv1, oacc[nt][3] * inv1, hh, ll);
        g_ATh[r1 + kp] = hh; g_ATl[r1 + kp] = ll;
    }
}

// ---------------------------------------------------------------------------
// Launch
// ---------------------------------------------------------------------------
extern "C" void kernel_launch(void* const* d_in, const int* in_sizes, int n_in,
                              void* d_out, int out_size) {
    const float* x    = (const float*)d_in[0];
    const float* Wqkv = (const float*)d_in[1];
    const float* bqkv = (const float*)d_in[2];
    const float* Wout = (const float*)d_in[3];
    const float* bout = (const float*)d_in[4];
    float* out = (float*)d_out;

    uint32_t *XH, *XL, *WQ, *WO, *ATh, *ATl;
    cudaGetSymbolAddress((void**)&XH,  g_XH);
    cudaGetSymbolAddress((void**)&XL,  g_XL);
    cudaGetSymbolAddress((void**)&WQ,  g_WQ);
    cudaGetSymbolAddress((void**)&WO,  g_WO);
    cudaGetSymbolAddress((void**)&ATh, g_ATh);
    cudaGetSymbolAddress((void**)&ATl, g_ATl);

    cudaFuncSetAttribute(gemm_sp<0>, cudaFuncAttributeMaxDynamicSharedMemorySize,
                         GEMM_SMEM_BYTES);
    cudaFuncSetAttribute(gemm_sp<1>, cudaFuncAttributeMaxDynamicSharedMemorySize,
                         GEMM_SMEM_BYTES);
    cudaFuncSetAttribute(attn_sp, cudaFuncAttributeMaxDynamicSharedMemorySize,
                         ATTN_SMEM_BYTES);

    // Prep: split x (fp16 hi/lo); weights to single fp16 B-planes
    {
        int nq = MTOT * CC / 4;
        split_A_kernel<<<(nq + 255) / 256, 256>>>(x, XH, XL, nq);
    }
    split_Bh_kernel<<<(KP * (C3 / 4) + 255) / 256, 256>>>(Wqkv, WQ, C3);
    split_Bh_kernel<<<(KP * (CC / 4) + 255) / 256, 256>>>(Wout, WO, CC);

    // 1) QKV projection with fused Q/K/V-layout epilogue
    gemm_sp<1><<<dim3(C3 / 128, MTOT / 128), 256, GEMM_SMEM_BYTES>>>(
        XH, XL, WQ, bqkv, nullptr, C3);

    // 2) Flash attention
    attn_sp<<<dim3(TT / 128, HH, BBATCH), 256, ATTN_SMEM_BYTES>>>();

    // 3) Output projection
    gemm_sp<0><<<dim3(CC / 128, MTOT / 128), 256, GEMM_SMEM_BYTES>>>(
        ATh, ATl, WO, bout, out, CC);
}

// round 12
// speedup vs baseline: 2.0713x; 1.4058x over previous
#include <cuda_runtime.h>
#include <cuda_fp16.h>
#include <math.h>
#include <stdint.h>

#define BBATCH 2
#define TT 2048
#define CC 1024
#define HH 16
#define C3 3072
#define MTOT 4096
#define KP 512          // k-pairs (1024/2)

// ---------------------------------------------------------------------------
// Scratch (__device__ globals; no allocation allowed) — all single fp16 planes
// ---------------------------------------------------------------------------
__device__ uint32_t g_Qp[(size_t)MTOT*512];              // Q fp16 pairs [row][col/2] (pre-scaled)
__device__ uint32_t g_K [(size_t)BBATCH*HH*TT*32];       // K fp16 packed [b,h,key,dp]
__device__ uint16_t g_V [(size_t)BBATCH*HH*TT*64];       // V fp16 [b,h,keypair,d]{key&1}
__device__ uint32_t g_X [(size_t)MTOT*KP];               // x fp16 pairs (A-plane)
__device__ uint32_t g_WQ[(size_t)KP*C3];                 // W_qkv fp16 pairs (B-plane)
__device__ uint32_t g_WO[(size_t)KP*CC];                 // W_out fp16 pairs
__device__ uint32_t g_AT[(size_t)MTOT*KP];               // attn out fp16 pairs (A-plane)

// ---------------------------------------------------------------------------
// helpers
// ---------------------------------------------------------------------------
__device__ __forceinline__ uint16_t h16(float x) {
    return __half_as_ushort(__float2half_rn(x));
}
__device__ __forceinline__ uint32_t pk(uint16_t a, uint16_t b) {
    return (uint32_t)a | ((uint32_t)b << 16);
}
__device__ __forceinline__ uint32_t sptr(const void* p) {
    return (uint32_t)__cvta_generic_to_shared(p);
}
__device__ __forceinline__ void ldm4(uint32_t* r, uint32_t addr) {
    asm volatile("ldmatrix.sync.aligned.m8n8.x4.shared.b16 {%0,%1,%2,%3}, [%4];"
        : "=r"(r[0]), "=r"(r[1]), "=r"(r[2]), "=r"(r[3]) : "r"(addr));
}
#define CP16(dst, src) \
    asm volatile("cp.async.cg.shared.global [%0], [%1], 16;\n" :: "r"(dst), "l"(src))
#define CP_COMMIT() asm volatile("cp.async.commit_group;\n")

__device__ __forceinline__ void mma16h(float* d, const uint32_t* a,
                                       uint32_t b0, uint32_t b1) {
    asm volatile(
        "mma.sync.aligned.m16n8k16.row.col.f32.f16.f16.f32 "
        "{%0,%1,%2,%3}, {%4,%5,%6,%7}, {%8,%9}, {%0,%1,%2,%3};\n"
        : "+f"(d[0]), "+f"(d[1]), "+f"(d[2]), "+f"(d[3])
        : "r"(a[0]), "r"(a[1]), "r"(a[2]), "r"(a[3]), "r"(b0), "r"(b1));
}

// ---------------------------------------------------------------------------
// Prep kernels
// ---------------------------------------------------------------------------
__global__ void pack_A_kernel(const float* __restrict__ src,
                              uint32_t* __restrict__ dst, int nquads) {
    int i = blockIdx.x * blockDim.x + threadIdx.x;
    if (i >= nquads) return;
    float4 v = ((const float4*)src)[i];
    ((uint2*)dst)[i] = make_uint2(pk(h16(v.x), h16(v.y)), pk(h16(v.z), h16(v.w)));
}
// W[K][N] -> fp16 B-plane: Wp[kp][n] = pk(W[2kp][n], W[2kp+1][n])
__global__ void pack_B_kernel(const float* __restrict__ W,
                              uint32_t* __restrict__ dst, int N) {
    int i = blockIdx.x * blockDim.x + threadIdx.x;
    int nq = N >> 2;
    if (i >= KP * nq) return;
    int kp = i / nq, c4 = (i - kp * nq) * 4;
    const float* p0 = W + (size_t)(2 * kp) * N + c4;
    float4 r0 = *(const float4*)p0;
    float4 r1 = *(const float4*)(p0 + N);
    uint4 hv;
    hv.x = pk(h16(r0.x), h16(r1.x));
    hv.y = pk(h16(r0.y), h16(r1.y));
    hv.z = pk(h16(r0.z), h16(r1.z));
    hv.w = pk(h16(r0.w), h16(r1.w));
    *(uint4*)(dst + (size_t)kp * N + c4) = hv;
}

// ---------------------------------------------------------------------------
// GEMM (single-pass fp16, fp32 accum): C = A16 @ B16 + bias
// BM=BN=128, BK=32 (16 kpairs), 256 threads (8 warps 2x4, warp tile 64x32).
// 3-buffer cp.async pipeline, 2-deep lookahead.
// EPI 0: fp32 C + bias.  EPI 1: QKV epilogue (Q fp16 packed / K fp16 / V fp16).
// ---------------------------------------------------------------------------
#define ASTG (128*20)
#define BSTG (16*136)
#define GEMM_SMEM_BYTES (3*(ASTG+BSTG)*4)   // 56832

template<int EPI>
__global__ void __launch_bounds__(256, 2)
gemm_sp(const uint32_t* __restrict__ Ap, const uint32_t* __restrict__ Bp,
        const float* __restrict__ bias, float* __restrict__ Cout, int N) {
    extern __shared__ uint32_t smg[];
    uint32_t* sA = smg;              // 3 stages of [128][20]
    uint32_t* sB = smg + 3 * ASTG;   // 3 stages of [16][136]

    const int tid = threadIdx.x;
    const int lane = tid & 31, wid = tid >> 5;
    const int g = lane >> 2, t = lane & 3;
    const int wm = (wid >> 2) * 64, wn = (wid & 3) * 32;
    const int bx = blockIdx.x, by = blockIdx.y;

    float acc[4][4][4];
#pragma unroll
    for (int i = 0; i < 4; i++)
#pragma unroll
        for (int j = 0; j < 4; j++)
#pragma unroll
            for (int r = 0; r < 4; r++) acc[i][j][r] = 0.0f;

    auto load_stage = [&](int st, int kp0) {
#pragma unroll
        for (int i = 0; i < 2; i++) {
            int id = tid + i * 256;
            int row = id >> 2, c = (id & 3) * 4;
            CP16(sptr(&sA[st * ASTG + row * 20 + c]),
                 Ap + (size_t)(by * 128 + row) * KP + kp0 + c);
        }
#pragma unroll
        for (int i = 0; i < 2; i++) {
            int id = tid + i * 256;
            int row = id >> 5, c = (id & 31) * 4;
            CP16(sptr(&sB[st * BSTG + row * 136 + c]),
                 Bp + (size_t)(kp0 + row) * N + bx * 128 + c);
        }
    };

    load_stage(0, 0);  CP_COMMIT();
    load_stage(1, 16); CP_COMMIT();

    const int NK = KP / 16;   // 32
    const int arow = lane & 15;
    const int ahalf = (lane >> 4) * 4;

    for (int k = 0; k < NK; k++) {
        int st = k % 3;
        if (k + 2 < NK) asm volatile("cp.async.wait_group 1;\n");
        else            asm volatile("cp.async.wait_group 0;\n");
        __syncthreads();
        if (k + 2 < NK) { load_stage((k + 2) % 3, (k + 2) * 16); CP_COMMIT(); }

#pragma unroll
        for (int s = 0; s < 2; s++) {
            const int acol = s * 8 + ahalf;
            uint32_t af[4][4], bf[4][2];
#pragma unroll
            for (int nt = 0; nt < 4; nt++) {
                bf[nt][0] = sB[st * BSTG + (s * 8 + t) * 136 + wn + nt * 8 + g];
                bf[nt][1] = sB[st * BSTG + (s * 8 + t + 4) * 136 + wn + nt * 8 + g];
            }
#pragma unroll
            for (int mt = 0; mt < 4; mt++)
                ldm4(af[mt], sptr(&sA[st * ASTG + (wm + mt * 16 + arow) * 20 + acol]));
#pragma unroll
            for (int mt = 0; mt < 4; mt++)
#pragma unroll
                for (int nt = 0; nt < 4; nt++)
                    mma16h(acc[mt][nt], af[mt], bf[nt][0], bf[nt][1]);
        }
    }

    // ---------------- epilogue ----------------
#pragma unroll
    for (int mt = 0; mt < 4; mt++) {
        int row = by * 128 + wm + mt * 16 + g;
#pragma unroll
        for (int nt = 0; nt < 4; nt++) {
            int col = bx * 128 + wn + nt * 8 + 2 * t;
            float b0v = bias[col], b1v = bias[col + 1];
            float v0 = acc[mt][nt][0] + b0v, v1 = acc[mt][nt][1] + b1v;
            float v2 = acc[mt][nt][2] + b0v, v3 = acc[mt][nt][3] + b1v;
            if (EPI == 0) {
                *(float2*)&Cout[(size_t)row * N + col]       = make_float2(v0, v1);
                *(float2*)&Cout[(size_t)(row + 8) * N + col] = make_float2(v2, v3);
            } else {
                int region = bx >> 3;   // uniform per block: 0=Q, 1=K, 2=V
                int b = row >> 11, key = row & (TT - 1);
                if (region == 0) {
                    // Q packed fp16, pre-scaled by 1/8
                    g_Qp[(size_t)row * 512 + (col >> 1)] =
                        pk(h16(v0 * 0.125f), h16(v1 * 0.125f));
                    g_Qp[(size_t)(row + 8) * 512 + (col >> 1)] =
                        pk(h16(v2 * 0.125f), h16(v3 * 0.125f));
                } else if (region == 1) {
                    int c2 = col - CC;
                    int h = c2 >> 6, dp = (c2 & 63) >> 1;
                    size_t r0 = ((size_t)(b * HH + h) * TT + key) * 32 + dp;
                    g_K[r0]          = pk(h16(v0), h16(v1));
                    g_K[r0 + 8 * 32] = pk(h16(v2), h16(v3));
                } else {
                    // V fp16, key-pair packed: u16 idx = (wbase + d)*2 + (key&1)
                    int c2 = col - 2 * CC;
                    int h = c2 >> 6, d = c2 & 63;
                    size_t wbase = ((size_t)(b * HH + h) * (TT >> 1) + (key >> 1)) * 64;
                    int par = key & 1;
                    g_V[(wbase + d)     * 2 + par] = h16(v0);
                    g_V[(wbase + d + 1) * 2 + par] = h16(v1);
                    size_t wbase8 = wbase + 4 * 64;   // key+8 -> kpair+4
                    g_V[(wbase8 + d)     * 2 + par] = h16(v2);
                    g_V[(wbase8 + d + 1) * 2 + par] = h16(v3);
                }
            }
        }
    }
}

// ---------------------------------------------------------------------------
// Flash attention: 256 threads (8 warps), q-tile 128, K/V tile 64,
// cp.async double-buffer, single-pass fp16 S = Q16 K16, fp16 P*V.
// grid (T/128, H, B).
// ---------------------------------------------------------------------------
#define KSTG (64*36)            // u32 per K stage
#define VSTG (32*72)            // u32 per V stage
#define PS_STRIDE 36
#define ATTN_SMEM_WORDS (2*KSTG + 2*VSTG + 8*16*PS_STRIDE)   // 13824
#define ATTN_SMEM_BYTES (ATTN_SMEM_WORDS * 4)                // 55296

__global__ void __launch_bounds__(256, 2)
attn_sp() {
    extern __shared__ uint32_t sma[];
    uint32_t* sKh = sma;                             // [2][64][36] fp16 pairs
    uint32_t* sVp = sma + 2 * KSTG;                  // [2][32][72] fp16 keypair x d
    uint32_t* sP  = sma + 2 * KSTG + 2 * VSTG;       // [8][16][36] half2 P

    const int tid = threadIdx.x;
    const int lane = tid & 31, wid = tid >> 5;
    const int g = lane >> 2, t = lane & 3;
    const int qt = blockIdx.x, h = blockIdx.y, b = blockIdx.z;
    const int bh = b * HH + h;
    const uint32_t* Kb  = g_K + (size_t)bh * TT * 32;
    const uint32_t* Vbp = (const uint32_t*)g_V + (size_t)bh * (TT >> 1) * 64;

    const int q0 = qt * 128 + wid * 16;
    const int grow = b * TT + q0;

    // Q fragments: direct packed-fp16 loads (already scaled by 1/8)
    uint32_t qf[4][4];
    {
        const uint32_t* Qa = g_Qp + (size_t)(grow + g) * 512 + h * 32;
        const uint32_t* Qb8 = g_Qp + (size_t)(grow + g + 8) * 512 + h * 32;
#pragma unroll
        for (int s = 0; s < 4; s++) {
            qf[s][0] = Qa [s * 8 + t];
            qf[s][1] = Qb8[s * 8 + t];
            qf[s][2] = Qa [s * 8 + t + 4];
            qf[s][3] = Qb8[s * 8 + t + 4];
        }
    }

    float mrow0 = -INFINITY, mrow1 = -INFINITY;
    float lrow0 = 0.0f, lrow1 = 0.0f;
    float oacc[8][4];
#pragma unroll
    for (int nt = 0; nt < 8; nt++)
#pragma unroll
        for (int r = 0; r < 4; r++) oacc[nt][r] = 0.0f;

    uint32_t* Pw = sP + wid * 16 * PS_STRIDE;

    auto load_tile = [&](int st, int kt) {
#pragma unroll
        for (int i = 0; i < 2; i++) {
            int id = tid + i * 256;
            int row = id >> 3, c = (id & 7) * 4;
            CP16(sptr(&sKh[st * KSTG + row * 36 + c]), Kb + (size_t)(kt + row) * 32 + c);
        }
#pragma unroll
        for (int i = 0; i < 2; i++) {
            int id = tid + i * 256;
            int row = id >> 4, c = (id & 15) * 4;
            CP16(sptr(&sVp[st * VSTG + row * 72 + c]),
                 Vbp + (size_t)((kt >> 1) + row) * 64 + c);
        }
    };

    load_tile(0, 0);
    CP_COMMIT();

    const int krow = lane & 15;
    const int khalf = (lane >> 4) * 4;

    for (int kti = 0; kti < TT / 64; kti++) {
        int st = kti & 1;
        asm volatile("cp.async.wait_group 0;\n");
        __syncthreads();
        if (kti + 1 < TT / 64) load_tile(st ^ 1, (kti + 1) * 64);
        CP_COMMIT();

        // S = Q K^T  (single-pass fp16) — ldmatrix K frags
        float sacc[8][4];
#pragma unroll
        for (int nt = 0; nt < 8; nt++)
#pragma unroll
            for (int r = 0; r < 4; r++) sacc[nt][r] = 0.0f;

#pragma unroll
        for (int npp = 0; npp < 4; npp++) {
            const int kb = npp * 16;
#pragma unroll
            for (int s = 0; s < 4; s++) {
                uint32_t kf[4];
                ldm4(kf, sptr(&sKh[st * KSTG + (kb + krow) * 36 + s * 8 + khalf]));
                mma16h(sacc[2*npp],     qf[s], kf[0], kf[2]);
                mma16h(sacc[2*npp + 1], qf[s], kf[1], kf[3]);
            }
        }

        // Online softmax
        float mx0 = -INFINITY, mx1 = -INFINITY;
#pragma unroll
        for (int nt = 0; nt < 8; nt++) {
            mx0 = fmaxf(mx0, fmaxf(sacc[nt][0], sacc[nt][1]));
            mx1 = fmaxf(mx1, fmaxf(sacc[nt][2], sacc[nt][3]));
        }
        mx0 = fmaxf(mx0, __shfl_xor_sync(0xffffffffu, mx0, 1));
        mx0 = fmaxf(mx0, __shfl_xor_sync(0xffffffffu, mx0, 2));
        mx1 = fmaxf(mx1, __shfl_xor_sync(0xffffffffu, mx1, 1));
        mx1 = fmaxf(mx1, __shfl_xor_sync(0xffffffffu, mx1, 2));

        float mn0 = fmaxf(mrow0, mx0);
        float mn1 = fmaxf(mrow1, mx1);
        float c0 = __expf(mrow0 - mn0);
        float c1 = __expf(mrow1 - mn1);
        lrow0 *= c0; lrow1 *= c1;
#pragma unroll
        for (int nt = 0; nt < 8; nt++) {
            oacc[nt][0] *= c0; oacc[nt][1] *= c0;
            oacc[nt][2] *= c1; oacc[nt][3] *= c1;
        }

        // P = exp(S - m), rounded to fp16 (consistent with l-sum)
        float s0 = 0.0f, s1 = 0.0f;
#pragma unroll
        for (int nt = 0; nt < 8; nt++) {
            __half2 H0 = __float22half2_rn(make_float2(__expf(sacc[nt][0] - mn0),
                                                       __expf(sacc[nt][1] - mn0)));
            __half2 H1 = __float22half2_rn(make_float2(__expf(sacc[nt][2] - mn1),
                                                       __expf(sacc[nt][3] - mn1)));
            float2 f0 = __half22float2(H0);
            float2 f1 = __half22float2(H1);
            s0 += f0.x + f0.y;
            s1 += f1.x + f1.y;
            Pw[(g    ) * PS_STRIDE + nt * 4 + t] = *(uint32_t*)&H0;
            Pw[(g + 8) * PS_STRIDE + nt * 4 + t] = *(uint32_t*)&H1;
        }
        s0 += __shfl_xor_sync(0xffffffffu, s0, 1);
        s0 += __shfl_xor_sync(0xffffffffu, s0, 2);
        s1 += __shfl_xor_sync(0xffffffffu, s1, 1);
        s1 += __shfl_xor_sync(0xffffffffu, s1, 2);
        lrow0 += s0; lrow1 += s1;
        mrow0 = mn0; mrow1 = mn1;

        __syncwarp();

        // O += P V   (fp16 m16n8k16): 4 k16 steps cover 64 keys
        const uint32_t* Vst = sVp + st * VSTG;
#pragma unroll
        for (int s = 0; s < 4; s++) {
            uint32_t pa[4];
            pa[0] = Pw[(g    ) * PS_STRIDE + s * 8 + t];
            pa[1] = Pw[(g + 8) * PS_STRIDE + s * 8 + t];
            pa[2] = Pw[(g    ) * PS_STRIDE + s * 8 + 4 + t];
            pa[3] = Pw[(g + 8) * PS_STRIDE + s * 8 + 4 + t];
#pragma unroll
            for (int nt = 0; nt < 8; nt++) {
                uint32_t b0 = Vst[(s * 8 + t    ) * 72 + nt * 8 + g];
                uint32_t b1 = Vst[(s * 8 + 4 + t) * 72 + nt * 8 + g];
                mma16h(oacc[nt], pa, b0, b1);
            }
        }
    }

    // Epilogue: normalize, write single fp16 plane (A-layout for out-proj)
    const float inv0 = 1.0f / lrow0;
    const float inv1 = 1.0f / lrow1;
    const size_t r0 = (size_t)(grow + g) * KP;
    const size_t r1 = (size_t)(grow + g + 8) * KP;
#pragma unroll
    for (int nt = 0; nt < 8; nt++) {
        int kp = h * 32 + nt * 4 + t;
        g_AT[r0 + kp] = pk(h16(oacc[nt][0] * inv0), h16(oacc[nt][1] * inv0));
        g_AT[r1 + kp] = pk(h16(oacc[nt][2] * inv1), h16(oacc[nt][3] * inv1));
    }
}

// ---------------------------------------------------------------------------
// Launch
// ---------------------------------------------------------------------------
extern "C" void kernel_launch(void* const* d_in, const int* in_sizes, int n_in,
                              void* d_out, int out_size) {
    const float* x    = (const float*)d_in[0];
    const float* Wqkv = (const float*)d_in[1];
    const float* bqkv = (const float*)d_in[2];
    const float* Wout = (const float*)d_in[3];
    const float* bout = (const float*)d_in[4];
    float* out = (float*)d_out;

    uint32_t *X, *WQ, *WO, *AT;
    cudaGetSymbolAddress((void**)&X,  g_X);
    cudaGetSymbolAddress((void**)&WQ, g_WQ);
    cudaGetSymbolAddress((void**)&WO, g_WO);
    cudaGetSymbolAddress((void**)&AT, g_AT);

    cudaFuncSetAttribute(gemm_sp<0>, cudaFuncAttributeMaxDynamicSharedMemorySize,
                         GEMM_SMEM_BYTES);
    cudaFuncSetAttribute(gemm_sp<1>, cudaFuncAttributeMaxDynamicSharedMemorySize,
                         GEMM_SMEM_BYTES);
    cudaFuncSetAttribute(attn_sp, cudaFuncAttributeMaxDynamicSharedMemorySize,
                         ATTN_SMEM_BYTES);

    // Prep: pack x and weights to fp16 planes
    {
        int nq = MTOT * CC / 4;
        pack_A_kernel<<<(nq + 255) / 256, 256>>>(x, X, nq);
    }
    pack_B_kernel<<<(KP * (C3 / 4) + 255) / 256, 256>>>(Wqkv, WQ, C3);
    pack_B_kernel<<<(KP * (CC / 4) + 255) / 256, 256>>>(Wout, WO, CC);

    // 1) QKV projection with fused Q/K/V-layout epilogue
    gemm_sp<1><<<dim3(C3 / 128, MTOT / 128), 256, GEMM_SMEM_BYTES>>>(
        X, WQ, bqkv, nullptr, C3);

    // 2) Flash attention
    attn_sp<<<dim3(TT / 128, HH, BBATCH), 256, ATTN_SMEM_BYTES>>>();

    // 3) Output projection
    gemm_sp<0><<<dim3(CC / 128, MTOT / 128), 256, GEMM_SMEM_BYTES>>>(
        AT, WO, bout, out, CC);
}

// round 14
// speedup vs baseline: 2.1586x; 1.0422x over previous
#include <cuda_runtime.h>
#include <cuda_fp16.h>
#include <math.h>
#include <stdint.h>

#define BBATCH 2
#define TT 2048
#define CC 1024
#define HH 16
#define C3 3072
#define MTOT 4096
#define KP 512          // k-pairs (1024/2)

// ---------------------------------------------------------------------------
// Scratch (__device__ globals; no allocation allowed) — all single fp16 planes
// ---------------------------------------------------------------------------
__device__ uint32_t g_Qp[(size_t)MTOT*512];              // Q fp16 pairs (pre-scaled by log2e/8)
__device__ uint32_t g_K [(size_t)BBATCH*HH*TT*32];       // K fp16 packed [b,h,key,dp]
__device__ uint16_t g_V [(size_t)BBATCH*HH*TT*64];       // V fp16 [b,h,keypair,d]{key&1}
__device__ uint32_t g_X [(size_t)MTOT*KP];               // x fp16 pairs (A-plane)
__device__ uint32_t g_WQ[(size_t)KP*C3];                 // W_qkv fp16 pairs (B-plane)
__device__ uint32_t g_WO[(size_t)KP*CC];                 // W_out fp16 pairs
__device__ uint32_t g_AT[(size_t)MTOT*KP];               // attn out fp16 pairs (A-plane)

// ---------------------------------------------------------------------------
// helpers
// ---------------------------------------------------------------------------
__device__ __forceinline__ uint16_t h16(float x) {
    return __half_as_ushort(__float2half_rn(x));
}
__device__ __forceinline__ uint32_t pk(uint16_t a, uint16_t b) {
    return (uint32_t)a | ((uint32_t)b << 16);
}
__device__ __forceinline__ float ex2(float x) {
    float r; asm("ex2.approx.f32 %0, %1;" : "=f"(r) : "f"(x)); return r;
}
__device__ __forceinline__ uint32_t sptr(const void* p) {
    return (uint32_t)__cvta_generic_to_shared(p);
}
__device__ __forceinline__ void ldm4(uint32_t* r, uint32_t addr) {
    asm volatile("ldmatrix.sync.aligned.m8n8.x4.shared.b16 {%0,%1,%2,%3}, [%4];"
        : "=r"(r[0]), "=r"(r[1]), "=r"(r[2]), "=r"(r[3]) : "r"(addr));
}
#define CP16(dst, src) \
    asm volatile("cp.async.cg.shared.global [%0], [%1], 16;\n" :: "r"(dst), "l"(src))
#define CP_COMMIT() asm volatile("cp.async.commit_group;\n")

__device__ __forceinline__ void mma16h(float* d, const uint32_t* a,
                                       uint32_t b0, uint32_t b1) {
    asm volatile(
        "mma.sync.aligned.m16n8k16.row.col.f32.f16.f16.f32 "
        "{%0,%1,%2,%3}, {%4,%5,%6,%7}, {%8,%9}, {%0,%1,%2,%3};\n"
        : "+f"(d[0]), "+f"(d[1]), "+f"(d[2]), "+f"(d[3])
        : "r"(a[0]), "r"(a[1]), "r"(a[2]), "r"(a[3]), "r"(b0), "r"(b1));
}

// ---------------------------------------------------------------------------
// Prep kernels
// ---------------------------------------------------------------------------
__global__ void pack_A_kernel(const float* __restrict__ src,
                              uint32_t* __restrict__ dst, int nquads) {
    int i = blockIdx.x * blockDim.x + threadIdx.x;
    if (i >= nquads) return;
    float4 v = ((const float4*)src)[i];
    ((uint2*)dst)[i] = make_uint2(pk(h16(v.x), h16(v.y)), pk(h16(v.z), h16(v.w)));
}
__global__ void pack_B_kernel(const float* __restrict__ W,
                              uint32_t* __restrict__ dst, int N) {
    int i = blockIdx.x * blockDim.x + threadIdx.x;
    int nq = N >> 2;
    if (i >= KP * nq) return;
    int kp = i / nq, c4 = (i - kp * nq) * 4;
    const float* p0 = W + (size_t)(2 * kp) * N + c4;
    float4 r0 = *(const float4*)p0;
    float4 r1 = *(const float4*)(p0 + N);
    uint4 hv;
    hv.x = pk(h16(r0.x), h16(r1.x));
    hv.y = pk(h16(r0.y), h16(r1.y));
    hv.z = pk(h16(r0.z), h16(r1.z));
    hv.w = pk(h16(r0.w), h16(r1.w));
    *(uint4*)(dst + (size_t)kp * N + c4) = hv;
}

// ---------------------------------------------------------------------------
// GEMM (single-pass fp16, fp32 accum): C = A16 @ B16 + bias
// BM=BN=128, BK=32 (16 kpairs), 256 threads, 3-buffer cp.async pipeline.
// EPI 0: fp32 C + bias.  EPI 1: QKV epilogue (Q fp16 packed / K fp16 / V fp16).
// ---------------------------------------------------------------------------
#define ASTG (128*20)
#define BSTG (16*136)
#define GEMM_SMEM_BYTES (3*(ASTG+BSTG)*4)   // 56832
#define QSCALE (0.125f * 1.44269504f)       // 1/sqrt(64) * log2(e)

template<int EPI>
__global__ void __launch_bounds__(256, 2)
gemm_sp(const uint32_t* __restrict__ Ap, const uint32_t* __restrict__ Bp,
        const float* __restrict__ bias, float* __restrict__ Cout, int N) {
    extern __shared__ uint32_t smg[];
    uint32_t* sA = smg;              // 3 stages of [128][20]
    uint32_t* sB = smg + 3 * ASTG;   // 3 stages of [16][136]

    const int tid = threadIdx.x;
    const int lane = tid & 31, wid = tid >> 5;
    const int g = lane >> 2, t = lane & 3;
    const int wm = (wid >> 2) * 64, wn = (wid & 3) * 32;
    const int bx = blockIdx.x, by = blockIdx.y;

    float acc[4][4][4];
#pragma unroll
    for (int i = 0; i < 4; i++)
#pragma unroll
        for (int j = 0; j < 4; j++)
#pragma unroll
            for (int r = 0; r < 4; r++) acc[i][j][r] = 0.0f;

    auto load_stage = [&](int st, int kp0) {
#pragma unroll
        for (int i = 0; i < 2; i++) {
            int id = tid + i * 256;
            int row = id >> 2, c = (id & 3) * 4;
            CP16(sptr(&sA[st * ASTG + row * 20 + c]),
                 Ap + (size_t)(by * 128 + row) * KP + kp0 + c);
        }
#pragma unroll
        for (int i = 0; i < 2; i++) {
            int id = tid + i * 256;
            int row = id >> 5, c = (id & 31) * 4;
            CP16(sptr(&sB[st * BSTG + row * 136 + c]),
                 Bp + (size_t)(kp0 + row) * N + bx * 128 + c);
        }
    };

    load_stage(0, 0);  CP_COMMIT();
    load_stage(1, 16); CP_COMMIT();

    const int NK = KP / 16;   // 32
    const int arow = lane & 15;
    const int ahalf = (lane >> 4) * 4;

    for (int k = 0; k < NK; k++) {
        int st = k % 3;
        if (k + 2 < NK) asm volatile("cp.async.wait_group 1;\n");
        else            asm volatile("cp.async.wait_group 0;\n");
        __syncthreads();
        if (k + 2 < NK) { load_stage((k + 2) % 3, (k + 2) * 16); CP_COMMIT(); }

#pragma unroll
        for (int s = 0; s < 2; s++) {
            const int acol = s * 8 + ahalf;
            uint32_t af[4][4], bf[4][2];
#pragma unroll
            for (int nt = 0; nt < 4; nt++) {
                bf[nt][0] = sB[st * BSTG + (s * 8 + t) * 136 + wn + nt * 8 + g];
                bf[nt][1] = sB[st * BSTG + (s * 8 + t + 4) * 136 + wn + nt * 8 + g];
            }
#pragma unroll
            for (int mt = 0; mt < 4; mt++)
                ldm4(af[mt], sptr(&sA[st * ASTG + (wm + mt * 16 + arow) * 20 + acol]));
#pragma unroll
            for (int mt = 0; mt < 4; mt++)
#pragma unroll
                for (int nt = 0; nt < 4; nt++)
                    mma16h(acc[mt][nt], af[mt], bf[nt][0], bf[nt][1]);
        }
    }

    // ---------------- epilogue ----------------
#pragma unroll
    for (int mt = 0; mt < 4; mt++) {
        int row = by * 128 + wm + mt * 16 + g;
#pragma unroll
        for (int nt = 0; nt < 4; nt++) {
            int col = bx * 128 + wn + nt * 8 + 2 * t;
            float b0v = bias[col], b1v = bias[col + 1];
            float v0 = acc[mt][nt][0] + b0v, v1 = acc[mt][nt][1] + b1v;
            float v2 = acc[mt][nt][2] + b0v, v3 = acc[mt][nt][3] + b1v;
            if (EPI == 0) {
                *(float2*)&Cout[(size_t)row * N + col]       = make_float2(v0, v1);
                *(float2*)&Cout[(size_t)(row + 8) * N + col] = make_float2(v2, v3);
            } else {
                int region = bx >> 3;   // uniform per block: 0=Q, 1=K, 2=V
                int b = row >> 11, key = row & (TT - 1);
                if (region == 0) {
                    // Q packed fp16, pre-scaled by log2e/8 (for ex2-softmax)
                    g_Qp[(size_t)row * 512 + (col >> 1)] =
                        pk(h16(v0 * QSCALE), h16(v1 * QSCALE));
                    g_Qp[(size_t)(row + 8) * 512 + (col >> 1)] =
                        pk(h16(v2 * QSCALE), h16(v3 * QSCALE));
                } else if (region == 1) {
                    int c2 = col - CC;
                    int h = c2 >> 6, dp = (c2 & 63) >> 1;
                    size_t r0 = ((size_t)(b * HH + h) * TT + key) * 32 + dp;
                    g_K[r0]          = pk(h16(v0), h16(v1));
                    g_K[r0 + 8 * 32] = pk(h16(v2), h16(v3));
                } else {
                    int c2 = col - 2 * CC;
                    int h = c2 >> 6, d = c2 & 63;
                    size_t wbase = ((size_t)(b * HH + h) * (TT >> 1) + (key >> 1)) * 64;
                    int par = key & 1;
                    g_V[(wbase + d)     * 2 + par] = h16(v0);
                    g_V[(wbase + d + 1) * 2 + par] = h16(v1);
                    size_t wbase8 = wbase + 4 * 64;   // key+8 -> kpair+4
                    g_V[(wbase8 + d)     * 2 + par] = h16(v2);
                    g_V[(wbase8 + d + 1) * 2 + par] = h16(v3);
                }
            }
        }
    }
}

// ---------------------------------------------------------------------------
// Flash attention: 256 threads (8 warps), q-tile 128, K/V tile 64,
// cp.async double-buffer, fp16 S = Q16 K16 (log2 domain), REGISTER-resident P
// (S C-layout == PV A-layout, no smem roundtrip), fp16 P*V.
// grid (T/128, H, B).
// ---------------------------------------------------------------------------
#define KSTG (64*36)            // u32 per K stage
#define VSTG (32*72)            // u32 per V stage
#define ATTN_SMEM_WORDS (2*KSTG + 2*VSTG)    // 9216
#define ATTN_SMEM_BYTES (ATTN_SMEM_WORDS * 4) // 36864

__global__ void __launch_bounds__(256, 2)
attn_sp() {
    extern __shared__ uint32_t sma[];
    uint32_t* sKh = sma;                 // [2][64][36] fp16 pairs
    uint32_t* sVp = sma + 2 * KSTG;      // [2][32][72] fp16 keypair x d

    const int tid = threadIdx.x;
    const int lane = tid & 31, wid = tid >> 5;
    const int g = lane >> 2, t = lane & 3;
    const int qt = blockIdx.x, h = blockIdx.y, b = blockIdx.z;
    const int bh = b * HH + h;
    const uint32_t* Kb  = g_K + (size_t)bh * TT * 32;
    const uint32_t* Vbp = (const uint32_t*)g_V + (size_t)bh * (TT >> 1) * 64;

    const int q0 = qt * 128 + wid * 16;
    const int grow = b * TT + q0;

    // Q fragments: direct packed-fp16 loads (already scaled by log2e/8)
    uint32_t qf[4][4];
    {
        const uint32_t* Qa  = g_Qp + (size_t)(grow + g) * 512 + h * 32;
        const uint32_t* Qb8 = g_Qp + (size_t)(grow + g + 8) * 512 + h * 32;
#pragma unroll
        for (int s = 0; s < 4; s++) {
            qf[s][0] = Qa [s * 8 + t];
            qf[s][1] = Qb8[s * 8 + t];
            qf[s][2] = Qa [s * 8 + t + 4];
            qf[s][3] = Qb8[s * 8 + t + 4];
        }
    }

    float mrow0 = -INFINITY, mrow1 = -INFINITY;
    float lrow0 = 0.0f, lrow1 = 0.0f;
    float oacc[8][4];
#pragma unroll
    for (int nt = 0; nt < 8; nt++)
#pragma unroll
        for (int r = 0; r < 4; r++) oacc[nt][r] = 0.0f;

    auto load_tile = [&](int st, int kt) {
#pragma unroll
        for (int i = 0; i < 2; i++) {
            int id = tid + i * 256;
            int row = id >> 3, c = (id & 7) * 4;
            CP16(sptr(&sKh[st * KSTG + row * 36 + c]), Kb + (size_t)(kt + row) * 32 + c);
        }
#pragma unroll
        for (int i = 0; i < 2; i++) {
            int id = tid + i * 256;
            int row = id >> 4, c = (id & 15) * 4;
            CP16(sptr(&sVp[st * VSTG + row * 72 + c]),
                 Vbp + (size_t)((kt >> 1) + row) * 64 + c);
        }
    };

    load_tile(0, 0);
    CP_COMMIT();

    const int krow = lane & 15;
    const int khalf = (lane >> 4) * 4;

    for (int kti = 0; kti < TT / 64; kti++) {
        int st = kti & 1;
        asm volatile("cp.async.wait_group 0;\n");
        __syncthreads();
        if (kti + 1 < TT / 64) load_tile(st ^ 1, (kti + 1) * 64);
        CP_COMMIT();

        // S = Q K^T  (fp16, log2 domain) — ldmatrix K frags
        float sacc[8][4];
#pragma unroll
        for (int nt = 0; nt < 8; nt++)
#pragma unroll
            for (int r = 0; r < 4; r++) sacc[nt][r] = 0.0f;

#pragma unroll
        for (int npp = 0; npp < 4; npp++) {
            const int kb = npp * 16;
#pragma unroll
            for (int s = 0; s < 4; s++) {
                uint32_t kf[4];
                ldm4(kf, sptr(&sKh[st * KSTG + (kb + krow) * 36 + s * 8 + khalf]));
                mma16h(sacc[2*npp],     qf[s], kf[0], kf[2]);
                mma16h(sacc[2*npp + 1], qf[s], kf[1], kf[3]);
            }
        }

        // Online softmax (base-2)
        float mx0 = -INFINITY, mx1 = -INFINITY;
#pragma unroll
        for (int nt = 0; nt < 8; nt++) {
            mx0 = fmaxf(mx0, fmaxf(sacc[nt][0], sacc[nt][1]));
            mx1 = fmaxf(mx1, fmaxf(sacc[nt][2], sacc[nt][3]));
        }
        mx0 = fmaxf(mx0, __shfl_xor_sync(0xffffffffu, mx0, 1));
        mx0 = fmaxf(mx0, __shfl_xor_sync(0xffffffffu, mx0, 2));
        mx1 = fmaxf(mx1, __shfl_xor_sync(0xffffffffu, mx1, 1));
        mx1 = fmaxf(mx1, __shfl_xor_sync(0xffffffffu, mx1, 2));

        float mn0 = fmaxf(mrow0, mx0);
        float mn1 = fmaxf(mrow1, mx1);
        float c0 = ex2(mrow0 - mn0);
        float c1 = ex2(mrow1 - mn1);
        lrow0 *= c0; lrow1 *= c1;
#pragma unroll
        for (int nt = 0; nt < 8; nt++) {
            oacc[nt][0] *= c0; oacc[nt][1] *= c0;
            oacc[nt][2] *= c1; oacc[nt][3] *= c1;
        }

        // Fused exp + P*V: P fragments formed directly in registers
        // (S C-layout == PV A-layout: nt=2s -> a0/a1, nt=2s+1 -> a2/a3)
        const uint32_t* Vst = sVp + st * VSTG;
        float s0 = 0.0f, s1 = 0.0f;
#pragma unroll
        for (int s = 0; s < 4; s++) {
            uint32_t pa[4];
            __half2 H;
            float2 f;
            H = __float22half2_rn(make_float2(ex2(sacc[2*s][0] - mn0),
                                              ex2(sacc[2*s][1] - mn0)));
            f = __half22float2(H); s0 += f.x + f.y; pa[0] = *(uint32_t*)&H;
            H = __float22half2_rn(make_float2(ex2(sacc[2*s][2] - mn1),
                                              ex2(sacc[2*s][3] - mn1)));
            f = __half22float2(H); s1 += f.x + f.y; pa[1] = *(uint32_t*)&H;
            H = __float22half2_rn(make_float2(ex2(sacc[2*s+1][0] - mn0),
                                              ex2(sacc[2*s+1][1] - mn0)));
            f = __half22float2(H); s0 += f.x + f.y; pa[2] = *(uint32_t*)&H;
            H = __float22half2_rn(make_float2(ex2(sacc[2*s+1][2] - mn1),
                                              ex2(sacc[2*s+1][3] - mn1)));
            f = __half22float2(H); s1 += f.x + f.y; pa[3] = *(uint32_t*)&H;
#pragma unroll
            for (int nt = 0; nt < 8; nt++) {
                uint32_t b0 = Vst[(s * 8 + t    ) * 72 + nt * 8 + g];
                uint32_t b1 = Vst[(s * 8 + 4 + t) * 72 + nt * 8 + g];
                mma16h(oacc[nt], pa, b0, b1);
            }
        }
        s0 += __shfl_xor_sync(0xffffffffu, s0, 1);
        s0 += __shfl_xor_sync(0xffffffffu, s0, 2);
        s1 += __shfl_xor_sync(0xffffffffu, s1, 1);
        s1 += __shfl_xor_sync(0xffffffffu, s1, 2);
        lrow0 += s0; lrow1 += s1;
        mrow0 = mn0; mrow1 = mn1;
    }

    // Epilogue: normalize, write single fp16 plane (A-layout for out-proj)
    const float inv0 = 1.0f / lrow0;
    const float inv1 = 1.0f / lrow1;
    const size_t r0 = (size_t)(grow + g) * KP;
    const size_t r1 = (size_t)(grow + g + 8) * KP;
#pragma unroll
    for (int nt = 0; nt < 8; nt++) {
        int kp = h * 32 + nt * 4 + t;
        g_AT[r0 + kp] = pk(h16(oacc[nt][0] * inv0), h16(oacc[nt][1] * inv0));
        g_AT[r1 + kp] = pk(h16(oacc[nt][2] * inv1), h16(oacc[nt][3] * inv1));
    }
}

// ---------------------------------------------------------------------------
// Launch
// ---------------------------------------------------------------------------
extern "C" void kernel_launch(void* const* d_in, const int* in_sizes, int n_in,
                              void* d_out, int out_size) {
    const float* x    = (const float*)d_in[0];
    const float* Wqkv = (const float*)d_in[1];
    const float* bqkv = (const float*)d_in[2];
    const float* Wout = (const float*)d_in[3];
    const float* bout = (const float*)d_in[4];
    float* out = (float*)d_out;

    uint32_t *X, *WQ, *WO, *AT;
    cudaGetSymbolAddress((void**)&X,  g_X);
    cudaGetSymbolAddress((void**)&WQ, g_WQ);
    cudaGetSymbolAddress((void**)&WO, g_WO);
    cudaGetSymbolAddress((void**)&AT, g_AT);

    cudaFuncSetAttribute(gemm_sp<0>, cudaFuncAttributeMaxDynamicSharedMemorySize,
                         GEMM_SMEM_BYTES);
    cudaFuncSetAttribute(gemm_sp<1>, cudaFuncAttributeMaxDynamicSharedMemorySize,
                         GEMM_SMEM_BYTES);
    cudaFuncSetAttribute(attn_sp, cudaFuncAttributeMaxDynamicSharedMemorySize,
                         ATTN_SMEM_BYTES);

    // Prep: pack x and weights to fp16 planes
    {
        int nq = MTOT * CC / 4;
        pack_A_kernel<<<(nq + 255) / 256, 256>>>(x, X, nq);
    }
    pack_B_kernel<<<(KP * (C3 / 4) + 255) / 256, 256>>>(Wqkv, WQ, C3);
    pack_B_kernel<<<(KP * (CC / 4) + 255) / 256, 256>>>(Wout, WO, CC);

    // 1) QKV projection with fused Q/K/V-layout epilogue
    gemm_sp<1><<<dim3(C3 / 128, MTOT / 128), 256, GEMM_SMEM_BYTES>>>(
        X, WQ, bqkv, nullptr, C3);

    // 2) Flash attention (register-resident P)
    attn_sp<<<dim3(TT / 128, HH, BBATCH), 256, ATTN_SMEM_BYTES>>>();

    // 3) Output projection
    gemm_sp<0><<<dim3(CC / 128, MTOT / 128), 256, GEMM_SMEM_BYTES>>>(
        AT, WO, bout, out, CC);
}

// round 15
// speedup vs baseline: 2.3074x; 1.0689x over previous
#include <cuda_runtime.h>
#include <cuda_fp16.h>
#include <math.h>
#include <stdint.h>

#define BBATCH 2
#define TT 2048
#define CC 1024
#define HH 16
#define C3 3072
#define MTOT 4096
#define KP 512          // k-pairs (1024/2)

// ---------------------------------------------------------------------------
// Scratch (__device__ globals; no allocation allowed) — all single fp16 planes
// ---------------------------------------------------------------------------
__device__ uint32_t g_Qp[(size_t)MTOT*512];              // Q fp16 pairs (pre-scaled log2e/8)
__device__ uint32_t g_K [(size_t)BBATCH*HH*TT*32];       // K fp16 packed [b,h,key,dp]
__device__ uint16_t g_V [(size_t)BBATCH*HH*64*TT];       // V fp16 [b,h,d,keypair]{par}
__device__ uint32_t g_X [(size_t)MTOT*KP];               // x fp16 pairs [row][kp]
__device__ uint32_t g_WQ[(size_t)C3*KP];                 // W_qkv^T fp16 pairs [n][kp]
__device__ uint32_t g_WO[(size_t)CC*KP];                 // W_out^T fp16 pairs [n][kp]
__device__ uint32_t g_AT[(size_t)MTOT*KP];               // attn out fp16 pairs [row][kp]

// ---------------------------------------------------------------------------
// helpers
// ---------------------------------------------------------------------------
__device__ __forceinline__ uint16_t h16(float x) {
    return __half_as_ushort(__float2half_rn(x));
}
__device__ __forceinline__ uint32_t pk(uint16_t a, uint16_t b) {
    return (uint32_t)a | ((uint32_t)b << 16);
}
__device__ __forceinline__ float ex2(float x) {
    float r; asm("ex2.approx.f32 %0, %1;" : "=f"(r) : "f"(x)); return r;
}
__device__ __forceinline__ uint32_t sptr(const void* p) {
    return (uint32_t)__cvta_generic_to_shared(p);
}
__device__ __forceinline__ void ldm4(uint32_t* r, uint32_t addr) {
    asm volatile("ldmatrix.sync.aligned.m8n8.x4.shared.b16 {%0,%1,%2,%3}, [%4];"
        : "=r"(r[0]), "=r"(r[1]), "=r"(r[2]), "=r"(r[3]) : "r"(addr));
}
#define CP16(dst, src) \
    asm volatile("cp.async.cg.shared.global [%0], [%1], 16;\n" :: "r"(dst), "l"(src))
#define CP_COMMIT() asm volatile("cp.async.commit_group;\n")

__device__ __forceinline__ void mma16h(float* d, const uint32_t* a,
                                       uint32_t b0, uint32_t b1) {
    asm volatile(
        "mma.sync.aligned.m16n8k16.row.col.f32.f16.f16.f32 "
        "{%0,%1,%2,%3}, {%4,%5,%6,%7}, {%8,%9}, {%0,%1,%2,%3};\n"
        : "+f"(d[0]), "+f"(d[1]), "+f"(d[2]), "+f"(d[3])
        : "r"(a[0]), "r"(a[1]), "r"(a[2]), "r"(a[3]), "r"(b0), "r"(b1));
}

// ---------------------------------------------------------------------------
// Prep kernels
// ---------------------------------------------------------------------------
__global__ void pack_A_kernel(const float* __restrict__ src,
                              uint32_t* __restrict__ dst, int nquads) {
    int i = blockIdx.x * blockDim.x + threadIdx.x;
    if (i >= nquads) return;
    float4 v = ((const float4*)src)[i];
    ((uint2*)dst)[i] = make_uint2(pk(h16(v.x), h16(v.y)), pk(h16(v.z), h16(v.w)));
}
// W[K][N] -> W^T fp16 plane [n][kp] via smem transpose (64x64 tiles)
__global__ void __launch_bounds__(256)
pack_WT_kernel(const float* __restrict__ W, uint32_t* __restrict__ dst, int N) {
    __shared__ uint16_t sh[64][66];
    const int bn = blockIdx.x * 64, bk = blockIdx.y * 64;
    const int tid = threadIdx.x;
#pragma unroll
    for (int r = 0; r < 4; r++) {
        int id = tid + r * 256;
        int kr = id >> 4;            // 0..63
        int nc = (id & 15) * 4;      // 0..60
        float4 v = *(const float4*)&W[(size_t)(bk + kr) * N + bn + nc];
        sh[nc + 0][kr] = h16(v.x);
        sh[nc + 1][kr] = h16(v.y);
        sh[nc + 2][kr] = h16(v.z);
        sh[nc + 3][kr] = h16(v.w);
    }
    __syncthreads();
#pragma unroll
    for (int r = 0; r < 2; r++) {
        int id = tid + r * 256;
        int nr = id >> 3;            // 0..63
        int q  = (id & 7) * 4;       // kp group 0..28
        uint4 hv;
        hv.x = pk(sh[nr][2*q+0], sh[nr][2*q+1]);
        hv.y = pk(sh[nr][2*q+2], sh[nr][2*q+3]);
        hv.z = pk(sh[nr][2*q+4], sh[nr][2*q+5]);
        hv.w = pk(sh[nr][2*q+6], sh[nr][2*q+7]);
        *(uint4*)&dst[(size_t)(bn + nr) * KP + (bk >> 1) + q] = hv;
    }
}

// ---------------------------------------------------------------------------
// GEMM (single-pass fp16, fp32 accum): C = A16 @ W16 + bias
// Both operands as [row][kp] planes; all fragment feeds via ldmatrix.x4.
// BM=BN=128, BK=32 (16 kpairs), 256 threads, 3-buffer cp.async pipeline.
// EPI 0: fp32 C + bias.  EPI 1: QKV epilogue (Q fp16 / K fp16 / V fp16 [d][kp]).
// ---------------------------------------------------------------------------
#define ASTG (128*20)
#define BSTG (128*20)
#define GEMM_SMEM_BYTES (3*(ASTG+BSTG)*4)   // 61440
#define QSCALE (0.125f * 1.44269504f)       // 1/sqrt(64) * log2(e)

template<int EPI>
__global__ void __launch_bounds__(256, 2)
gemm_sp(const uint32_t* __restrict__ Ap, const uint32_t* __restrict__ Bp,
        const float* __restrict__ bias, float* __restrict__ Cout, int N) {
    extern __shared__ uint32_t smg[];
    uint32_t* sA = smg;              // 3 stages of [128][20]
    uint32_t* sB = smg + 3 * ASTG;   // 3 stages of [128][20]

    const int tid = threadIdx.x;
    const int lane = tid & 31, wid = tid >> 5;
    const int g = lane >> 2, t = lane & 3;
    const int wm = (wid >> 2) * 64, wn = (wid & 3) * 32;
    const int bx = blockIdx.x, by = blockIdx.y;

    float acc[4][4][4];
#pragma unroll
    for (int i = 0; i < 4; i++)
#pragma unroll
        for (int j = 0; j < 4; j++)
#pragma unroll
            for (int r = 0; r < 4; r++) acc[i][j][r] = 0.0f;

    auto load_stage = [&](int st, int kp0) {
#pragma unroll
        for (int i = 0; i < 2; i++) {
            int id = tid + i * 256;
            int row = id >> 2, c = (id & 3) * 4;
            CP16(sptr(&sA[st * ASTG + row * 20 + c]),
                 Ap + (size_t)(by * 128 + row) * KP + kp0 + c);
            CP16(sptr(&sB[st * BSTG + row * 20 + c]),
                 Bp + (size_t)(bx * 128 + row) * KP + kp0 + c);
        }
    };

    load_stage(0, 0);  CP_COMMIT();
    load_stage(1, 16); CP_COMMIT();

    const int NK = KP / 16;   // 32
    const int arow = lane & 15;
    const int ahalf = (lane >> 4) * 4;
    const int bmrow = ((lane >> 3) >> 1) * 8 + (lane & 7);  // matrix-pair row
    const int bcol  = ((lane >> 3) & 1) * 4;                // b0/b1 word half

    for (int k = 0; k < NK; k++) {
        int st = k % 3;
        if (k + 2 < NK) asm volatile("cp.async.wait_group 1;\n");
        else            asm volatile("cp.async.wait_group 0;\n");
        __syncthreads();
        if (k + 2 < NK) { load_stage((k + 2) % 3, (k + 2) * 16); CP_COMMIT(); }

#pragma unroll
        for (int s = 0; s < 2; s++) {
            const int acol = s * 8 + ahalf;
            uint32_t af[4][4], bf0[4], bf1[4];
            ldm4(bf0, sptr(&sB[st * BSTG + (wn + bmrow) * 20 + s * 8 + bcol]));
            ldm4(bf1, sptr(&sB[st * BSTG + (wn + 16 + bmrow) * 20 + s * 8 + bcol]));
#pragma unroll
            for (int mt = 0; mt < 4; mt++)
                ldm4(af[mt], sptr(&sA[st * ASTG + (wm + mt * 16 + arow) * 20 + acol]));
#pragma unroll
            for (int mt = 0; mt < 4; mt++) {
                mma16h(acc[mt][0], af[mt], bf0[0], bf0[1]);
                mma16h(acc[mt][1], af[mt], bf0[2], bf0[3]);
                mma16h(acc[mt][2], af[mt], bf1[0], bf1[1]);
                mma16h(acc[mt][3], af[mt], bf1[2], bf1[3]);
            }
        }
    }

    // ---------------- epilogue ----------------
#pragma unroll
    for (int mt = 0; mt < 4; mt++) {
        int row = by * 128 + wm + mt * 16 + g;
#pragma unroll
        for (int nt = 0; nt < 4; nt++) {
            int col = bx * 128 + wn + nt * 8 + 2 * t;
            float b0v = bias[col], b1v = bias[col + 1];
            float v0 = acc[mt][nt][0] + b0v, v1 = acc[mt][nt][1] + b1v;
            float v2 = acc[mt][nt][2] + b0v, v3 = acc[mt][nt][3] + b1v;
            if (EPI == 0) {
                *(float2*)&Cout[(size_t)row * N + col]       = make_float2(v0, v1);
                *(float2*)&Cout[(size_t)(row + 8) * N + col] = make_float2(v2, v3);
            } else {
                int region = bx >> 3;   // uniform per block: 0=Q, 1=K, 2=V
                int b = row >> 11, key = row & (TT - 1);
                if (region == 0) {
                    g_Qp[(size_t)row * 512 + (col >> 1)] =
                        pk(h16(v0 * QSCALE), h16(v1 * QSCALE));
                    g_Qp[(size_t)(row + 8) * 512 + (col >> 1)] =
                        pk(h16(v2 * QSCALE), h16(v3 * QSCALE));
                } else if (region == 1) {
                    int c2 = col - CC;
                    int h = c2 >> 6, dp = (c2 & 63) >> 1;
                    size_t r0 = ((size_t)(b * HH + h) * TT + key) * 32 + dp;
                    g_K[r0]          = pk(h16(v0), h16(v1));
                    g_K[r0 + 8 * 32] = pk(h16(v2), h16(v3));
                } else {
                    // V fp16, [b,h,d,keypair]: u16 idx = word*2 + (key&1)
                    int c2 = col - 2 * CC;
                    int h = c2 >> 6, d = c2 & 63;
                    size_t vb = ((size_t)(b * HH + h) * 64 + d) * (TT >> 1) + (key >> 1);
                    int par = key & 1;
                    g_V[vb * 2 + par]                     = h16(v0);  // d,   key
                    g_V[(vb + (TT >> 1)) * 2 + par]       = h16(v1);  // d+1, key
                    g_V[(vb + 4) * 2 + par]               = h16(v2);  // d,   key+8
                    g_V[(vb + (TT >> 1) + 4) * 2 + par]   = h16(v3);  // d+1, key+8
                }
            }
        }
    }
}

// ---------------------------------------------------------------------------
// Flash attention: 256 threads (8 warps), q-tile 128, K/V tile 64,
// cp.async double-buffer, fp16 S (log2 domain), register-resident P,
// V fed via ldmatrix from [d][keypair] smem. grid (T/128, H, B).
// ---------------------------------------------------------------------------
#define KSTG (64*36)            // u32 per K stage
#define VSTG (64*36)            // u32 per V stage ([64 d][32 kp] + pad)
#define ATTN_SMEM_WORDS (2*KSTG + 2*VSTG)    // 9216
#define ATTN_SMEM_BYTES (ATTN_SMEM_WORDS * 4) // 36864

__global__ void __launch_bounds__(256, 2)
attn_sp() {
    extern __shared__ uint32_t sma[];
    uint32_t* sKh = sma;                 // [2][64 key][36] fp16 pairs
    uint32_t* sV2 = sma + 2 * KSTG;      // [2][64 d][36]  fp16 keypair words

    const int tid = threadIdx.x;
    const int lane = tid & 31, wid = tid >> 5;
    const int g = lane >> 2, t = lane & 3;
    const int qt = blockIdx.x, h = blockIdx.y, b = blockIdx.z;
    const int bh = b * HH + h;
    const uint32_t* Kb  = g_K + (size_t)bh * TT * 32;
    const uint32_t* Vbp = (const uint32_t*)g_V + (size_t)bh * 64 * (TT >> 1);

    const int q0 = qt * 128 + wid * 16;
    const int grow = b * TT + q0;

    // Q fragments: direct packed-fp16 loads (already scaled by log2e/8)
    uint32_t qf[4][4];
    {
        const uint32_t* Qa  = g_Qp + (size_t)(grow + g) * 512 + h * 32;
        const uint32_t* Qb8 = g_Qp + (size_t)(grow + g + 8) * 512 + h * 32;
#pragma unroll
        for (int s = 0; s < 4; s++) {
            qf[s][0] = Qa [s * 8 + t];
            qf[s][1] = Qb8[s * 8 + t];
            qf[s][2] = Qa [s * 8 + t + 4];
            qf[s][3] = Qb8[s * 8 + t + 4];
        }
    }

    float mrow0 = -INFINITY, mrow1 = -INFINITY;
    float lrow0 = 0.0f, lrow1 = 0.0f;
    float oacc[8][4];
#pragma unroll
    for (int nt = 0; nt < 8; nt++)
#pragma unroll
        for (int r = 0; r < 4; r++) oacc[nt][r] = 0.0f;

    auto load_tile = [&](int st, int kt) {
#pragma unroll
        for (int i = 0; i < 2; i++) {
            int id = tid + i * 256;
            int row = id >> 3, c = (id & 7) * 4;
            CP16(sptr(&sKh[st * KSTG + row * 36 + c]), Kb + (size_t)(kt + row) * 32 + c);
            CP16(sptr(&sV2[st * VSTG + row * 36 + c]),
                 Vbp + (size_t)row * (TT >> 1) + (kt >> 1) + c);
        }
    };

    load_tile(0, 0);
    CP_COMMIT();

    const int krow = lane & 15;
    const int khalf = (lane >> 4) * 4;
    const int vmrow = ((lane >> 3) >> 1) * 8 + (lane & 7);
    const int vcol  = ((lane >> 3) & 1) * 4;

    for (int kti = 0; kti < TT / 64; kti++) {
        int st = kti & 1;
        asm volatile("cp.async.wait_group 0;\n");
        __syncthreads();
        if (kti + 1 < TT / 64) load_tile(st ^ 1, (kti + 1) * 64);
        CP_COMMIT();

        // S = Q K^T  (fp16, log2 domain) — ldmatrix K frags
        float sacc[8][4];
#pragma unroll
        for (int nt = 0; nt < 8; nt++)
#pragma unroll
            for (int r = 0; r < 4; r++) sacc[nt][r] = 0.0f;

#pragma unroll
        for (int npp = 0; npp < 4; npp++) {
            const int kb = npp * 16;
#pragma unroll
            for (int s = 0; s < 4; s++) {
                uint32_t kf[4];
                ldm4(kf, sptr(&sKh[st * KSTG + (kb + krow) * 36 + s * 8 + khalf]));
                mma16h(sacc[2*npp],     qf[s], kf[0], kf[2]);
                mma16h(sacc[2*npp + 1], qf[s], kf[1], kf[3]);
            }
        }

        // Online softmax (base-2)
        float mx0 = -INFINITY, mx1 = -INFINITY;
#pragma unroll
        for (int nt = 0; nt < 8; nt++) {
            mx0 = fmaxf(mx0, fmaxf(sacc[nt][0], sacc[nt][1]));
            mx1 = fmaxf(mx1, fmaxf(sacc[nt][2], sacc[nt][3]));
        }
        mx0 = fmaxf(mx0, __shfl_xor_sync(0xffffffffu, mx0, 1));
        mx0 = fmaxf(mx0, __shfl_xor_sync(0xffffffffu, mx0, 2));
        mx1 = fmaxf(mx1, __shfl_xor_sync(0xffffffffu, mx1, 1));
        mx1 = fmaxf(mx1, __shfl_xor_sync(0xffffffffu, mx1, 2));

        float mn0 = fmaxf(mrow0, mx0);
        float mn1 = fmaxf(mrow1, mx1);
        float c0 = ex2(mrow0 - mn0);
        float c1 = ex2(mrow1 - mn1);
        lrow0 *= c0; lrow1 *= c1;
#pragma unroll
        for (int nt = 0; nt < 8; nt++) {
            oacc[nt][0] *= c0; oacc[nt][1] *= c0;
            oacc[nt][2] *= c1; oacc[nt][3] *= c1;
        }

        // Fused exp + P*V, V frags via ldmatrix from [d][kp] smem
        const uint32_t* Vst = sV2 + st * VSTG;
        float s0 = 0.0f, s1 = 0.0f;
#pragma unroll
        for (int s = 0; s < 4; s++) {
            uint32_t pa[4];
            __half2 H;
            float2 f;
            H = __float22half2_rn(make_float2(ex2(sacc[2*s][0] - mn0),
                                              ex2(sacc[2*s][1] - mn0)));
            f = __half22float2(H); s0 += f.x + f.y; pa[0] = *(uint32_t*)&H;
            H = __float22half2_rn(make_float2(ex2(sacc[2*s][2] - mn1),
                                              ex2(sacc[2*s][3] - mn1)));
            f = __half22float2(H); s1 += f.x + f.y; pa[1] = *(uint32_t*)&H;
            H = __float22half2_rn(make_float2(ex2(sacc[2*s+1][0] - mn0),
                                              ex2(sacc[2*s+1][1] - mn0)));
            f = __half22float2(H); s0 += f.x + f.y; pa[2] = *(uint32_t*)&H;
            H = __float22half2_rn(make_float2(ex2(sacc[2*s+1][2] - mn1),
                                              ex2(sacc[2*s+1][3] - mn1)));
            f = __half22float2(H); s1 += f.x + f.y; pa[3] = *(uint32_t*)&H;
#pragma unroll
            for (int np = 0; np < 4; np++) {
                uint32_t vf[4];
                ldm4(vf, sptr(&Vst[(np * 16 + vmrow) * 36 + s * 8 + vcol]));
                mma16h(oacc[2*np],     pa, vf[0], vf[1]);
                mma16h(oacc[2*np + 1], pa, vf[2], vf[3]);
            }
        }
        s0 += __shfl_xor_sync(0xffffffffu, s0, 1);
        s0 += __shfl_xor_sync(0xffffffffu, s0, 2);
        s1 += __shfl_xor_sync(0xffffffffu, s1, 1);
        s1 += __shfl_xor_sync(0xffffffffu, s1, 2);
        lrow0 += s0; lrow1 += s1;
        mrow0 = mn0; mrow1 = mn1;
    }

    // Epilogue: normalize, write single fp16 plane (A-layout for out-proj)
    const float inv0 = 1.0f / lrow0;
    const float inv1 = 1.0f / lrow1;
    const size_t r0 = (size_t)(grow + g) * KP;
    const size_t r1 = (size_t)(grow + g + 8) * KP;
#pragma unroll
    for (int nt = 0; nt < 8; nt++) {
        int kp = h * 32 + nt * 4 + t;
        g_AT[r0 + kp] = pk(h16(oacc[nt][0] * inv0), h16(oacc[nt][1] * inv0));
        g_AT[r1 + kp] = pk(h16(oacc[nt][2] * inv1), h16(oacc[nt][3] * inv1));
    }
}

// ---------------------------------------------------------------------------
// Launch
// ---------------------------------------------------------------------------
extern "C" void kernel_launch(void* const* d_in, const int* in_sizes, int n_in,
                              void* d_out, int out_size) {
    const float* x    = (const float*)d_in[0];
    const float* Wqkv = (const float*)d_in[1];
    const float* bqkv = (const float*)d_in[2];
    const float* Wout = (const float*)d_in[3];
    const float* bout = (const float*)d_in[4];
    float* out = (float*)d_out;

    uint32_t *X, *WQ, *WO, *AT;
    cudaGetSymbolAddress((void**)&X,  g_X);
    cudaGetSymbolAddress((void**)&WQ, g_WQ);
    cudaGetSymbolAddress((void**)&WO, g_WO);
    cudaGetSymbolAddress((void**)&AT, g_AT);

    cudaFuncSetAttribute(gemm_sp<0>, cudaFuncAttributeMaxDynamicSharedMemorySize,
                         GEMM_SMEM_BYTES);
    cudaFuncSetAttribute(gemm_sp<1>, cudaFuncAttributeMaxDynamicSharedMemorySize,
                         GEMM_SMEM_BYTES);
    cudaFuncSetAttribute(attn_sp, cudaFuncAttributeMaxDynamicSharedMemorySize,
                         ATTN_SMEM_BYTES);

    // Prep: pack x; transpose-pack weights to [n][kp] planes
    {
        int nq = MTOT * CC / 4;
        pack_A_kernel<<<(nq + 255) / 256, 256>>>(x, X, nq);
    }
    pack_WT_kernel<<<dim3(C3 / 64, 16), 256>>>(Wqkv, WQ, C3);
    pack_WT_kernel<<<dim3(CC / 64, 16), 256>>>(Wout, WO, CC);

    // 1) QKV projection with fused Q/K/V-layout epilogue
    gemm_sp<1><<<dim3(C3 / 128, MTOT / 128), 256, GEMM_SMEM_BYTES>>>(
        X, WQ, bqkv, nullptr, C3);

    // 2) Flash attention (register P, ldmatrix V)
    attn_sp<<<dim3(TT / 128, HH, BBATCH), 256, ATTN_SMEM_BYTES>>>();

    // 3) Output projection
    gemm_sp<0><<<dim3(CC / 128, MTOT / 128), 256, GEMM_SMEM_BYTES>>>(
        AT, WO, bout, out, CC);
}